// round 3
// baseline (speedup 1.0000x reference)
#include <cuda_runtime.h>

#define NN 100000
#define DD 128
#define EE 1600000
#define WPAD 132   // padded row stride for 256x128 transposed weights in smem
#define HPAD 66    // padded row stride for 128x64 transposed head weights

// ---------------- scratch (device globals; no allocations allowed) ----------
// NOTE: __align__(16) is load-bearing — these are accessed via float4*.
__device__ __align__(16) float g_agg [(size_t)NN * DD];  // aggregation accumulator
__device__ __align__(16) float g_hpre[(size_t)NN * DD];  // pre-BN activations
__device__ __align__(16) float g_h1  [(size_t)NN * DD];  // post-BN/ReLU layer-1
__device__ int   g_deg [NN];
__device__ float g_invdeg[NN];
__device__ float g_colsum[DD];
__device__ float g_colsq [DD];
__device__ __align__(16) float g_scale[DD];
__device__ __align__(16) float g_shift[DD];

// ---------------- init: agg = x (self loop), deg = 1, zero BN stats ---------
__global__ void init_kernel(const float* __restrict__ x) {
    int idx = blockIdx.x * blockDim.x + threadIdx.x;
    if (idx < NN * 32) {
        ((float4*)g_agg)[idx] = ((const float4*)x)[idx];
    }
    if (idx < NN) g_deg[idx] = 1;
    if (idx < DD) { g_colsum[idx] = 0.f; g_colsq[idx] = 0.f; }
}

// ---------------- edge aggregation: warp per edge, both directions ----------
// edge_index is int32 on device (JAX default config downcasts int64 randint).
template<bool FIRST>
__global__ void edge_kernel(const int* __restrict__ ei,
                            const float* __restrict__ xin) {
    long long gtid = (long long)blockIdx.x * blockDim.x + threadIdx.x;
    int e = (int)(gtid >> 5);
    if (e >= EE) return;
    int lane = threadIdx.x & 31;
    const float* feat = FIRST ? xin : g_h1;
    int a = ei[e];
    int b = ei[EE + e];
    int c = lane * 4;
    float4 fa = *(const float4*)(feat + (size_t)a * DD + c);
    float4 fb = *(const float4*)(feat + (size_t)b * DD + c);
    float* pa = g_agg + (size_t)a * DD + c;
    float* pb = g_agg + (size_t)b * DD + c;
    atomicAdd(pb + 0, fa.x); atomicAdd(pb + 1, fa.y);
    atomicAdd(pb + 2, fa.z); atomicAdd(pb + 3, fa.w);
    atomicAdd(pa + 0, fb.x); atomicAdd(pa + 1, fb.y);
    atomicAdd(pa + 2, fb.z); atomicAdd(pa + 3, fb.w);
    if (FIRST && lane == 0) {
        atomicAdd(&g_deg[a], 1);
        atomicAdd(&g_deg[b], 1);
    }
}

__global__ void invdeg_kernel() {
    int i = blockIdx.x * blockDim.x + threadIdx.x;
    if (i < NN) g_invdeg[i] = 1.0f / (float)g_deg[i];
}

// ---------------- fused dual GEMM: hpre = A@Wa^T + (agg*invdeg)@Wb^T + bias -
template<int LAYER>
__global__ void __launch_bounds__(512, 1) gemm_dual_kernel(
    const float* __restrict__ xin,
    const float* __restrict__ Wa, const float* __restrict__ Wb,
    const float* __restrict__ ba, const float* __restrict__ bb) {
    extern __shared__ float sm[];
    float* sW  = sm;                 // 256 rows x WPAD
    float* sIn = sm + 256 * WPAD;    // 64 nodes x 256
    const float* A = (LAYER == 0) ? xin : g_h1;
    const float* B = g_agg;
    int tid = threadIdx.x;

    for (int i = tid; i < DD * DD; i += 512) {
        int f = i >> 7, k = i & 127;
        sW[k * WPAD + f]        = Wa[i];
        sW[(k + DD) * WPAD + f] = Wb[i];
    }

    int warp = tid >> 5, lane = tid & 31;
    int f0 = lane * 4;
    float bs0 = ba[f0 + 0] + bb[f0 + 0];
    float bs1 = ba[f0 + 1] + bb[f0 + 1];
    float bs2 = ba[f0 + 2] + bb[f0 + 2];
    float bs3 = ba[f0 + 3] + bb[f0 + 3];
    float cs0 = 0.f, cs1 = 0.f, cs2 = 0.f, cs3 = 0.f;
    float cq0 = 0.f, cq1 = 0.f, cq2 = 0.f, cq3 = 0.f;

    const int NT = (NN + 63) / 64;
    for (int tile = blockIdx.x; tile < NT; tile += gridDim.x) {
        int base = tile * 64;
        __syncthreads();   // previous tile fully consumed (covers sW 1st iter)
        for (int i = tid; i < 64 * 32; i += 512) {
            int n = i >> 5, q = i & 31;
            int node = base + n;
            float4 v = make_float4(0.f, 0.f, 0.f, 0.f);
            float4 u = make_float4(0.f, 0.f, 0.f, 0.f);
            if (node < NN) {
                v = *(const float4*)(A + (size_t)node * DD + q * 4);
                float id = g_invdeg[node];
                u = *(const float4*)(B + (size_t)node * DD + q * 4);
                u.x *= id; u.y *= id; u.z *= id; u.w *= id;
            }
            *(float4*)(sIn + n * 256 + q * 4)      = v;
            *(float4*)(sIn + n * 256 + DD + q * 4) = u;
        }
        __syncthreads();

        float acc[4][4];
        #pragma unroll
        for (int i = 0; i < 4; i++)
            #pragma unroll
            for (int j = 0; j < 4; j++) acc[i][j] = 0.f;

        const float* in0 = sIn + (warp * 4 + 0) * 256;
        const float* in1 = sIn + (warp * 4 + 1) * 256;
        const float* in2 = sIn + (warp * 4 + 2) * 256;
        const float* in3 = sIn + (warp * 4 + 3) * 256;

        for (int k = 0; k < 256; k += 4) {
            float4 v0 = *(const float4*)(in0 + k);
            float4 v1 = *(const float4*)(in1 + k);
            float4 v2 = *(const float4*)(in2 + k);
            float4 v3 = *(const float4*)(in3 + k);
            #pragma unroll
            for (int kk = 0; kk < 4; kk++) {
                float4 wv = *(const float4*)(sW + (k + kk) * WPAD + f0);
                float e;
                e = ((const float*)&v0)[kk];
                acc[0][0] += wv.x * e; acc[0][1] += wv.y * e;
                acc[0][2] += wv.z * e; acc[0][3] += wv.w * e;
                e = ((const float*)&v1)[kk];
                acc[1][0] += wv.x * e; acc[1][1] += wv.y * e;
                acc[1][2] += wv.z * e; acc[1][3] += wv.w * e;
                e = ((const float*)&v2)[kk];
                acc[2][0] += wv.x * e; acc[2][1] += wv.y * e;
                acc[2][2] += wv.z * e; acc[2][3] += wv.w * e;
                e = ((const float*)&v3)[kk];
                acc[3][0] += wv.x * e; acc[3][1] += wv.y * e;
                acc[3][2] += wv.z * e; acc[3][3] += wv.w * e;
            }
        }

        #pragma unroll
        for (int nidx = 0; nidx < 4; nidx++) {
            int node = base + warp * 4 + nidx;
            if (node < NN) {
                float o0 = acc[nidx][0] + bs0;
                float o1 = acc[nidx][1] + bs1;
                float o2 = acc[nidx][2] + bs2;
                float o3 = acc[nidx][3] + bs3;
                float4 o = make_float4(o0, o1, o2, o3);
                *(float4*)(g_hpre + (size_t)node * DD + f0) = o;
                cs0 += o0; cq0 += o0 * o0;
                cs1 += o1; cq1 += o1 * o1;
                cs2 += o2; cq2 += o2 * o2;
                cs3 += o3; cq3 += o3 * o3;
            }
        }
    }

    atomicAdd(&g_colsum[f0 + 0], cs0); atomicAdd(&g_colsq[f0 + 0], cq0);
    atomicAdd(&g_colsum[f0 + 1], cs1); atomicAdd(&g_colsq[f0 + 1], cq1);
    atomicAdd(&g_colsum[f0 + 2], cs2); atomicAdd(&g_colsq[f0 + 2], cq2);
    atomicAdd(&g_colsum[f0 + 3], cs3); atomicAdd(&g_colsq[f0 + 3], cq3);
}

// ---------------- BN finalize: stats -> scale/shift, reset stats ------------
__global__ void bn_finalize_kernel(const float* __restrict__ gamma,
                                   const float* __restrict__ beta) {
    int c = threadIdx.x;
    float mean = g_colsum[c] * (1.0f / NN);
    float var  = g_colsq[c]  * (1.0f / NN) - mean * mean;
    float sc   = gamma[c] * rsqrtf(var + 1e-5f);
    g_scale[c] = sc;
    g_shift[c] = beta[c] - mean * sc;
    g_colsum[c] = 0.f;
    g_colsq[c]  = 0.f;
}

// ---------------- apply BN+ReLU; also seeds layer-2 self-loop agg -----------
__global__ void apply_bn_kernel() {
    int idx = blockIdx.x * blockDim.x + threadIdx.x;
    if (idx >= NN * 32) return;
    int q = idx & 31;
    float4 v  = ((const float4*)g_hpre)[idx];
    float4 sc = *(const float4*)(g_scale + q * 4);
    float4 sh = *(const float4*)(g_shift + q * 4);
    v.x = fmaxf(v.x * sc.x + sh.x, 0.f);
    v.y = fmaxf(v.y * sc.y + sh.y, 0.f);
    v.z = fmaxf(v.z * sc.z + sh.z, 0.f);
    v.w = fmaxf(v.w * sc.w + sh.w, 0.f);
    ((float4*)g_h1)[idx]  = v;
    ((float4*)g_agg)[idx] = v;
}

// ---------------- head: out = relu(bn(hpre)) @ Wh^T + bh  (fused BN) --------
__global__ void __launch_bounds__(512, 2) head_kernel(
    const float* __restrict__ Wh, const float* __restrict__ bh,
    float* __restrict__ outp) {
    extern __shared__ float sm[];
    float* sW  = sm;              // 128 rows x HPAD (transposed 64x128 head W)
    float* sIn = sm + DD * HPAD;  // 64 nodes x 128
    int tid = threadIdx.x;

    for (int i = tid; i < 64 * DD; i += 512) {
        int f = i >> 7, k = i & 127;
        sW[k * HPAD + f] = Wh[i];
    }

    int base = blockIdx.x * 64;
    for (int i = tid; i < 64 * 32; i += 512) {
        int n = i >> 5, q = i & 31;
        int node = base + n;
        float4 v = make_float4(0.f, 0.f, 0.f, 0.f);
        if (node < NN) {
            v = ((const float4*)(g_hpre + (size_t)node * DD))[q];
            float4 sc = *(const float4*)(g_scale + q * 4);
            float4 sh = *(const float4*)(g_shift + q * 4);
            v.x = fmaxf(v.x * sc.x + sh.x, 0.f);
            v.y = fmaxf(v.y * sc.y + sh.y, 0.f);
            v.z = fmaxf(v.z * sc.z + sh.z, 0.f);
            v.w = fmaxf(v.w * sc.w + sh.w, 0.f);
        }
        *(float4*)(sIn + n * DD + q * 4) = v;
    }
    __syncthreads();

    int warp = tid >> 5, lane = tid & 31;
    int f0 = lane * 2;
    float b0 = bh[f0], b1 = bh[f0 + 1];
    float acc[4][2];
    #pragma unroll
    for (int i = 0; i < 4; i++) { acc[i][0] = 0.f; acc[i][1] = 0.f; }

    const float* in0 = sIn + (warp * 4 + 0) * DD;
    const float* in1 = sIn + (warp * 4 + 1) * DD;
    const float* in2 = sIn + (warp * 4 + 2) * DD;
    const float* in3 = sIn + (warp * 4 + 3) * DD;

    for (int k = 0; k < DD; k += 4) {
        float4 v0 = *(const float4*)(in0 + k);
        float4 v1 = *(const float4*)(in1 + k);
        float4 v2 = *(const float4*)(in2 + k);
        float4 v3 = *(const float4*)(in3 + k);
        #pragma unroll
        for (int kk = 0; kk < 4; kk++) {
            float2 wv = *(const float2*)(sW + (k + kk) * HPAD + f0);
            float e;
            e = ((const float*)&v0)[kk]; acc[0][0] += wv.x * e; acc[0][1] += wv.y * e;
            e = ((const float*)&v1)[kk]; acc[1][0] += wv.x * e; acc[1][1] += wv.y * e;
            e = ((const float*)&v2)[kk]; acc[2][0] += wv.x * e; acc[2][1] += wv.y * e;
            e = ((const float*)&v3)[kk]; acc[3][0] += wv.x * e; acc[3][1] += wv.y * e;
        }
    }

    #pragma unroll
    for (int nidx = 0; nidx < 4; nidx++) {
        int node = base + warp * 4 + nidx;
        if (node < NN) {
            float2 o = make_float2(acc[nidx][0] + b0, acc[nidx][1] + b1);
            *(float2*)(outp + (size_t)node * 64 + f0) = o;
        }
    }
}

// ---------------- launch ----------------------------------------------------
extern "C" void kernel_launch(void* const* d_in, const int* in_sizes, int n_in,
                              void* d_out, int out_size) {
    const float* x   = (const float*)d_in[0];
    const int*   ei  = (const int*)d_in[1];     // int32! JAX downcasts int64
    const float* Ws1 = (const float*)d_in[2];
    const float* bs1 = (const float*)d_in[3];
    const float* Wn1 = (const float*)d_in[4];
    const float* bn1 = (const float*)d_in[5];
    const float* g1  = (const float*)d_in[6];
    const float* be1 = (const float*)d_in[7];
    const float* Ws2 = (const float*)d_in[8];
    const float* bs2 = (const float*)d_in[9];
    const float* Wn2 = (const float*)d_in[10];
    const float* bn2 = (const float*)d_in[11];
    const float* g2  = (const float*)d_in[12];
    const float* be2 = (const float*)d_in[13];
    const float* Wh  = (const float*)d_in[14];
    const float* bh  = (const float*)d_in[15];
    float* out = (float*)d_out;

    const int GEMM_SMEM = (256 * WPAD + 64 * 256) * 4;   // 200704 B
    const int HEAD_SMEM = (DD * HPAD + 64 * DD) * 4;     // 66560 B
    cudaFuncSetAttribute(gemm_dual_kernel<0>,
                         cudaFuncAttributeMaxDynamicSharedMemorySize, GEMM_SMEM);
    cudaFuncSetAttribute(gemm_dual_kernel<1>,
                         cudaFuncAttributeMaxDynamicSharedMemorySize, GEMM_SMEM);
    cudaFuncSetAttribute(head_kernel,
                         cudaFuncAttributeMaxDynamicSharedMemorySize, HEAD_SMEM);

    // layer 1
    init_kernel<<<(NN * 32 + 255) / 256, 256>>>(x);
    edge_kernel<true><<<EE / 8, 256>>>(ei, x);
    invdeg_kernel<<<(NN + 255) / 256, 256>>>();
    gemm_dual_kernel<0><<<148, 512, GEMM_SMEM>>>(x, Ws1, Wn1, bs1, bn1);
    bn_finalize_kernel<<<1, 128>>>(g1, be1);
    apply_bn_kernel<<<(NN * 32 + 255) / 256, 256>>>();

    // layer 2
    edge_kernel<false><<<EE / 8, 256>>>(ei, x);
    gemm_dual_kernel<1><<<148, 512, GEMM_SMEM>>>(x, Ws2, Wn2, bs2, bn2);
    bn_finalize_kernel<<<1, 128>>>(g2, be2);

    // head
    head_kernel<<<(NN + 63) / 64, 512, HEAD_SMEM>>>(Wh, bh, out);
}

// round 5
// speedup vs baseline: 2.4153x; 2.4153x over previous
#include <cuda_runtime.h>

#define NN 100000
#define DD 128
#define EE 1600000
#define WPAD 132   // padded row stride for 256x128 transposed weights in smem
#define HPAD 66    // padded row stride for 128x64 transposed head weights

// ---------------- scratch (device globals; no allocations allowed) ----------
__device__ __align__(16) float g_agg [(size_t)NN * DD];  // normalized aggregation
__device__ __align__(16) float g_hpre[(size_t)NN * DD];  // pre-BN activations
__device__ __align__(16) float g_h1  [(size_t)NN * DD];  // post-BN/ReLU layer-1
__device__ int   g_deg   [NN];        // directed-incidence count (excl. self loop)
__device__ int   g_cursor[NN];
__device__ int   g_rowptr[NN + 1];
__device__ int   g_col   [2 * EE];
__device__ float g_colsum[DD];
__device__ float g_colsq [DD];
__device__ __align__(16) float g_scale[DD];
__device__ __align__(16) float g_shift[DD];

// ---------------- CSR build --------------------------------------------------
__global__ void zero_kernel() {
    int i = blockIdx.x * blockDim.x + threadIdx.x;
    if (i < NN) { g_deg[i] = 0; g_cursor[i] = 0; }
    if (i < DD) { g_colsum[i] = 0.f; g_colsq[i] = 0.f; }
}

__global__ void count_kernel(const int* __restrict__ ei) {
    int e = blockIdx.x * blockDim.x + threadIdx.x;
    if (e >= EE) return;
    int a = ei[e], b = ei[EE + e];
    atomicAdd(&g_deg[a], 1);
    atomicAdd(&g_deg[b], 1);
}

// single-block scan over g_deg -> g_rowptr
__global__ void scan_kernel() {
    __shared__ int warp_sums[32];
    int tid = threadIdx.x;            // 1024 threads
    int lane = tid & 31, wid = tid >> 5;
    int running = 0;
    for (int base = 0; base < NN; base += 1024) {
        int i = base + tid;
        int v = (i < NN) ? g_deg[i] : 0;
        int x = v;
        #pragma unroll
        for (int o = 1; o < 32; o <<= 1) {
            int y = __shfl_up_sync(0xffffffffu, x, o);
            if (lane >= o) x += y;
        }
        if (lane == 31) warp_sums[wid] = x;
        __syncthreads();
        if (wid == 0) {
            int s = warp_sums[lane];
            #pragma unroll
            for (int o = 1; o < 32; o <<= 1) {
                int y = __shfl_up_sync(0xffffffffu, s, o);
                if (lane >= o) s += y;
            }
            warp_sums[lane] = s;
        }
        __syncthreads();
        int incl = running + (wid > 0 ? warp_sums[wid - 1] : 0) + x;
        if (i < NN) g_rowptr[i + 1] = incl;
        running += warp_sums[31];
        __syncthreads();
    }
    if (tid == 0) g_rowptr[0] = 0;
}

__global__ void scatter_kernel(const int* __restrict__ ei) {
    int e = blockIdx.x * blockDim.x + threadIdx.x;
    if (e >= EE) return;
    int a = ei[e], b = ei[EE + e];
    int pb = g_rowptr[b] + atomicAdd(&g_cursor[b], 1);
    g_col[pb] = a;
    int pa = g_rowptr[a] + atomicAdd(&g_cursor[a], 1);
    g_col[pa] = b;
}

// ---------------- gather-side mean aggregation: warp per node ----------------
// agg[i] = (feat[i] + sum_{j in adj(i)} feat[j]) / (deg_i + 1)
// LAYER selects feat source inside device code (no device symbols from host!).
template<int LAYER>
__global__ void __launch_bounds__(256) aggregate_kernel(
    const float* __restrict__ xin) {
    const float* feat = (LAYER == 0) ? xin : g_h1;
    int node = (int)((blockIdx.x * blockDim.x + threadIdx.x) >> 5);
    if (node >= NN) return;
    int lane = threadIdx.x & 31;
    int c = lane * 4;

    float4 acc = *(const float4*)(feat + (size_t)node * DD + c);  // self loop
    int s = g_rowptr[node];
    int e = g_rowptr[node + 1];

    int j = s;
    for (; j + 4 <= e; j += 4) {
        int n0 = g_col[j + 0], n1 = g_col[j + 1];
        int n2 = g_col[j + 2], n3 = g_col[j + 3];
        float4 v0 = *(const float4*)(feat + (size_t)n0 * DD + c);
        float4 v1 = *(const float4*)(feat + (size_t)n1 * DD + c);
        float4 v2 = *(const float4*)(feat + (size_t)n2 * DD + c);
        float4 v3 = *(const float4*)(feat + (size_t)n3 * DD + c);
        acc.x += v0.x + v1.x + v2.x + v3.x;
        acc.y += v0.y + v1.y + v2.y + v3.y;
        acc.z += v0.z + v1.z + v2.z + v3.z;
        acc.w += v0.w + v1.w + v2.w + v3.w;
    }
    for (; j < e; j++) {
        int nb = g_col[j];
        float4 v = *(const float4*)(feat + (size_t)nb * DD + c);
        acc.x += v.x; acc.y += v.y; acc.z += v.z; acc.w += v.w;
    }

    float inv = 1.0f / (float)(e - s + 1);
    acc.x *= inv; acc.y *= inv; acc.z *= inv; acc.w *= inv;
    *(float4*)(g_agg + (size_t)node * DD + c) = acc;
}

// ---------------- fused dual GEMM: hpre = A@Wa^T + agg@Wb^T + bias ----------
template<int LAYER>
__global__ void __launch_bounds__(512, 1) gemm_dual_kernel(
    const float* __restrict__ xin,
    const float* __restrict__ Wa, const float* __restrict__ Wb,
    const float* __restrict__ ba, const float* __restrict__ bb) {
    extern __shared__ float sm[];
    float* sW  = sm;                 // 256 rows x WPAD
    float* sIn = sm + 256 * WPAD;    // 64 nodes x 256
    const float* A = (LAYER == 0) ? xin : g_h1;
    const float* B = g_agg;
    int tid = threadIdx.x;

    for (int i = tid; i < DD * DD; i += 512) {
        int f = i >> 7, k = i & 127;
        sW[k * WPAD + f]        = Wa[i];
        sW[(k + DD) * WPAD + f] = Wb[i];
    }

    int warp = tid >> 5, lane = tid & 31;
    int f0 = lane * 4;
    float bs0 = ba[f0 + 0] + bb[f0 + 0];
    float bs1 = ba[f0 + 1] + bb[f0 + 1];
    float bs2 = ba[f0 + 2] + bb[f0 + 2];
    float bs3 = ba[f0 + 3] + bb[f0 + 3];
    float cs0 = 0.f, cs1 = 0.f, cs2 = 0.f, cs3 = 0.f;
    float cq0 = 0.f, cq1 = 0.f, cq2 = 0.f, cq3 = 0.f;

    const int NT = (NN + 63) / 64;
    for (int tile = blockIdx.x; tile < NT; tile += gridDim.x) {
        int base = tile * 64;
        __syncthreads();   // previous tile fully consumed (covers sW 1st iter)
        for (int i = tid; i < 64 * 32; i += 512) {
            int n = i >> 5, q = i & 31;
            int node = base + n;
            float4 v = make_float4(0.f, 0.f, 0.f, 0.f);
            float4 u = make_float4(0.f, 0.f, 0.f, 0.f);
            if (node < NN) {
                v = *(const float4*)(A + (size_t)node * DD + q * 4);
                u = *(const float4*)(B + (size_t)node * DD + q * 4);
            }
            *(float4*)(sIn + n * 256 + q * 4)      = v;
            *(float4*)(sIn + n * 256 + DD + q * 4) = u;
        }
        __syncthreads();

        float acc[4][4];
        #pragma unroll
        for (int i = 0; i < 4; i++)
            #pragma unroll
            for (int j = 0; j < 4; j++) acc[i][j] = 0.f;

        const float* in0 = sIn + (warp * 4 + 0) * 256;
        const float* in1 = sIn + (warp * 4 + 1) * 256;
        const float* in2 = sIn + (warp * 4 + 2) * 256;
        const float* in3 = sIn + (warp * 4 + 3) * 256;

        for (int k = 0; k < 256; k += 4) {
            float4 v0 = *(const float4*)(in0 + k);
            float4 v1 = *(const float4*)(in1 + k);
            float4 v2 = *(const float4*)(in2 + k);
            float4 v3 = *(const float4*)(in3 + k);
            #pragma unroll
            for (int kk = 0; kk < 4; kk++) {
                float4 wv = *(const float4*)(sW + (k + kk) * WPAD + f0);
                float e;
                e = ((const float*)&v0)[kk];
                acc[0][0] += wv.x * e; acc[0][1] += wv.y * e;
                acc[0][2] += wv.z * e; acc[0][3] += wv.w * e;
                e = ((const float*)&v1)[kk];
                acc[1][0] += wv.x * e; acc[1][1] += wv.y * e;
                acc[1][2] += wv.z * e; acc[1][3] += wv.w * e;
                e = ((const float*)&v2)[kk];
                acc[2][0] += wv.x * e; acc[2][1] += wv.y * e;
                acc[2][2] += wv.z * e; acc[2][3] += wv.w * e;
                e = ((const float*)&v3)[kk];
                acc[3][0] += wv.x * e; acc[3][1] += wv.y * e;
                acc[3][2] += wv.z * e; acc[3][3] += wv.w * e;
            }
        }

        #pragma unroll
        for (int nidx = 0; nidx < 4; nidx++) {
            int node = base + warp * 4 + nidx;
            if (node < NN) {
                float o0 = acc[nidx][0] + bs0;
                float o1 = acc[nidx][1] + bs1;
                float o2 = acc[nidx][2] + bs2;
                float o3 = acc[nidx][3] + bs3;
                float4 o = make_float4(o0, o1, o2, o3);
                *(float4*)(g_hpre + (size_t)node * DD + f0) = o;
                cs0 += o0; cq0 += o0 * o0;
                cs1 += o1; cq1 += o1 * o1;
                cs2 += o2; cq2 += o2 * o2;
                cs3 += o3; cq3 += o3 * o3;
            }
        }
    }

    atomicAdd(&g_colsum[f0 + 0], cs0); atomicAdd(&g_colsq[f0 + 0], cq0);
    atomicAdd(&g_colsum[f0 + 1], cs1); atomicAdd(&g_colsq[f0 + 1], cq1);
    atomicAdd(&g_colsum[f0 + 2], cs2); atomicAdd(&g_colsq[f0 + 2], cq2);
    atomicAdd(&g_colsum[f0 + 3], cs3); atomicAdd(&g_colsq[f0 + 3], cq3);
}

// ---------------- BN finalize: stats -> scale/shift, reset stats ------------
__global__ void bn_finalize_kernel(const float* __restrict__ gamma,
                                   const float* __restrict__ beta) {
    int c = threadIdx.x;
    float mean = g_colsum[c] * (1.0f / NN);
    float var  = g_colsq[c]  * (1.0f / NN) - mean * mean;
    float sc   = gamma[c] * rsqrtf(var + 1e-5f);
    g_scale[c] = sc;
    g_shift[c] = beta[c] - mean * sc;
    g_colsum[c] = 0.f;
    g_colsq[c]  = 0.f;
}

// ---------------- apply BN+ReLU -> g_h1 -------------------------------------
__global__ void apply_bn_kernel() {
    int idx = blockIdx.x * blockDim.x + threadIdx.x;
    if (idx >= NN * 32) return;
    int q = idx & 31;
    float4 v  = ((const float4*)g_hpre)[idx];
    float4 sc = *(const float4*)(g_scale + q * 4);
    float4 sh = *(const float4*)(g_shift + q * 4);
    v.x = fmaxf(v.x * sc.x + sh.x, 0.f);
    v.y = fmaxf(v.y * sc.y + sh.y, 0.f);
    v.z = fmaxf(v.z * sc.z + sh.z, 0.f);
    v.w = fmaxf(v.w * sc.w + sh.w, 0.f);
    ((float4*)g_h1)[idx] = v;
}

// ---------------- head: out = relu(bn(hpre)) @ Wh^T + bh  (fused BN) --------
__global__ void __launch_bounds__(512, 2) head_kernel(
    const float* __restrict__ Wh, const float* __restrict__ bh,
    float* __restrict__ outp) {
    extern __shared__ float sm[];
    float* sW  = sm;              // 128 rows x HPAD
    float* sIn = sm + DD * HPAD;  // 64 nodes x 128
    int tid = threadIdx.x;

    for (int i = tid; i < 64 * DD; i += 512) {
        int f = i >> 7, k = i & 127;
        sW[k * HPAD + f] = Wh[i];
    }

    int base = blockIdx.x * 64;
    for (int i = tid; i < 64 * 32; i += 512) {
        int n = i >> 5, q = i & 31;
        int node = base + n;
        float4 v = make_float4(0.f, 0.f, 0.f, 0.f);
        if (node < NN) {
            v = ((const float4*)(g_hpre + (size_t)node * DD))[q];
            float4 sc = *(const float4*)(g_scale + q * 4);
            float4 sh = *(const float4*)(g_shift + q * 4);
            v.x = fmaxf(v.x * sc.x + sh.x, 0.f);
            v.y = fmaxf(v.y * sc.y + sh.y, 0.f);
            v.z = fmaxf(v.z * sc.z + sh.z, 0.f);
            v.w = fmaxf(v.w * sc.w + sh.w, 0.f);
        }
        *(float4*)(sIn + n * DD + q * 4) = v;
    }
    __syncthreads();

    int warp = tid >> 5, lane = tid & 31;
    int f0 = lane * 2;
    float b0 = bh[f0], b1 = bh[f0 + 1];
    float acc[4][2];
    #pragma unroll
    for (int i = 0; i < 4; i++) { acc[i][0] = 0.f; acc[i][1] = 0.f; }

    const float* in0 = sIn + (warp * 4 + 0) * DD;
    const float* in1 = sIn + (warp * 4 + 1) * DD;
    const float* in2 = sIn + (warp * 4 + 2) * DD;
    const float* in3 = sIn + (warp * 4 + 3) * DD;

    for (int k = 0; k < DD; k += 4) {
        float4 v0 = *(const float4*)(in0 + k);
        float4 v1 = *(const float4*)(in1 + k);
        float4 v2 = *(const float4*)(in2 + k);
        float4 v3 = *(const float4*)(in3 + k);
        #pragma unroll
        for (int kk = 0; kk < 4; kk++) {
            float2 wv = *(const float2*)(sW + (k + kk) * HPAD + f0);
            float e;
            e = ((const float*)&v0)[kk]; acc[0][0] += wv.x * e; acc[0][1] += wv.y * e;
            e = ((const float*)&v1)[kk]; acc[1][0] += wv.x * e; acc[1][1] += wv.y * e;
            e = ((const float*)&v2)[kk]; acc[2][0] += wv.x * e; acc[2][1] += wv.y * e;
            e = ((const float*)&v3)[kk]; acc[3][0] += wv.x * e; acc[3][1] += wv.y * e;
        }
    }

    #pragma unroll
    for (int nidx = 0; nidx < 4; nidx++) {
        int node = base + warp * 4 + nidx;
        if (node < NN) {
            float2 o = make_float2(acc[nidx][0] + b0, acc[nidx][1] + b1);
            *(float2*)(outp + (size_t)node * 64 + f0) = o;
        }
    }
}

// ---------------- launch ----------------------------------------------------
extern "C" void kernel_launch(void* const* d_in, const int* in_sizes, int n_in,
                              void* d_out, int out_size) {
    const float* x   = (const float*)d_in[0];
    const int*   ei  = (const int*)d_in[1];     // int32 (JAX default int)
    const float* Ws1 = (const float*)d_in[2];
    const float* bs1 = (const float*)d_in[3];
    const float* Wn1 = (const float*)d_in[4];
    const float* bn1 = (const float*)d_in[5];
    const float* g1  = (const float*)d_in[6];
    const float* be1 = (const float*)d_in[7];
    const float* Ws2 = (const float*)d_in[8];
    const float* bs2 = (const float*)d_in[9];
    const float* Wn2 = (const float*)d_in[10];
    const float* bn2 = (const float*)d_in[11];
    const float* g2  = (const float*)d_in[12];
    const float* be2 = (const float*)d_in[13];
    const float* Wh  = (const float*)d_in[14];
    const float* bh  = (const float*)d_in[15];
    float* out = (float*)d_out;

    const int GEMM_SMEM = (256 * WPAD + 64 * 256) * 4;   // 200704 B
    const int HEAD_SMEM = (DD * HPAD + 64 * DD) * 4;     // 66560 B
    cudaFuncSetAttribute(gemm_dual_kernel<0>,
                         cudaFuncAttributeMaxDynamicSharedMemorySize, GEMM_SMEM);
    cudaFuncSetAttribute(gemm_dual_kernel<1>,
                         cudaFuncAttributeMaxDynamicSharedMemorySize, GEMM_SMEM);
    cudaFuncSetAttribute(head_kernel,
                         cudaFuncAttributeMaxDynamicSharedMemorySize, HEAD_SMEM);

    // CSR build (once; reused by both layers)
    zero_kernel<<<(NN + 255) / 256, 256>>>();
    count_kernel<<<(EE + 255) / 256, 256>>>(ei);
    scan_kernel<<<1, 1024>>>();
    scatter_kernel<<<(EE + 255) / 256, 256>>>(ei);

    // layer 1
    aggregate_kernel<0><<<(NN * 32 + 255) / 256, 256>>>(x);
    gemm_dual_kernel<0><<<148, 512, GEMM_SMEM>>>(x, Ws1, Wn1, bs1, bn1);
    bn_finalize_kernel<<<1, 128>>>(g1, be1);
    apply_bn_kernel<<<(NN * 32 + 255) / 256, 256>>>();

    // layer 2
    aggregate_kernel<1><<<(NN * 32 + 255) / 256, 256>>>(x);
    gemm_dual_kernel<1><<<148, 512, GEMM_SMEM>>>(x, Ws2, Wn2, bs2, bn2);
    bn_finalize_kernel<<<1, 128>>>(g2, be2);

    // head
    head_kernel<<<(NN + 63) / 64, 512, HEAD_SMEM>>>(Wh, bh, out);
}

// round 8
// speedup vs baseline: 2.6019x; 1.0773x over previous
#include <cuda_runtime.h>

#define NN 100000
#define DD 128
#define EE 1600000
#define HPAD 66    // padded row stride for 128x64 transposed head weights

// ---------------- scratch (device globals; no allocations allowed) ----------
__device__ __align__(16) float g_agg [(size_t)NN * DD];  // normalized aggregation
__device__ __align__(16) float g_hpre[(size_t)NN * DD];  // pre-BN activations
__device__ __align__(16) float g_h1  [(size_t)NN * DD];  // post-BN/ReLU layer-1
__device__ int   g_deg   [NN];
__device__ int   g_cursor[NN];
__device__ int   g_rowptr[NN + 1];
__device__ int   g_col   [2 * EE];
__device__ float g_colsum[DD];
__device__ float g_colsq [DD];
__device__ __align__(16) float g_scale[DD];
__device__ __align__(16) float g_shift[DD];

// ---------------- CSR build --------------------------------------------------
__global__ void zero_kernel() {
    int i = blockIdx.x * blockDim.x + threadIdx.x;
    if (i < NN) { g_deg[i] = 0; g_cursor[i] = 0; }
    if (i < DD) { g_colsum[i] = 0.f; g_colsq[i] = 0.f; }
}

__global__ void count_kernel(const int* __restrict__ ei) {
    int e = blockIdx.x * blockDim.x + threadIdx.x;
    if (e >= EE) return;
    int a = ei[e], b = ei[EE + e];
    atomicAdd(&g_deg[a], 1);
    atomicAdd(&g_deg[b], 1);
}

// single-block scan over g_deg -> g_rowptr
__global__ void scan_kernel() {
    __shared__ int warp_sums[32];
    int tid = threadIdx.x;            // 1024 threads
    int lane = tid & 31, wid = tid >> 5;
    int running = 0;
    for (int base = 0; base < NN; base += 1024) {
        int i = base + tid;
        int v = (i < NN) ? g_deg[i] : 0;
        int x = v;
        #pragma unroll
        for (int o = 1; o < 32; o <<= 1) {
            int y = __shfl_up_sync(0xffffffffu, x, o);
            if (lane >= o) x += y;
        }
        if (lane == 31) warp_sums[wid] = x;
        __syncthreads();
        if (wid == 0) {
            int s = warp_sums[lane];
            #pragma unroll
            for (int o = 1; o < 32; o <<= 1) {
                int y = __shfl_up_sync(0xffffffffu, s, o);
                if (lane >= o) s += y;
            }
            warp_sums[lane] = s;
        }
        __syncthreads();
        int incl = running + (wid > 0 ? warp_sums[wid - 1] : 0) + x;
        if (i < NN) g_rowptr[i + 1] = incl;
        running += warp_sums[31];
        __syncthreads();
    }
    if (tid == 0) g_rowptr[0] = 0;
}

__global__ void scatter_kernel(const int* __restrict__ ei) {
    int e = blockIdx.x * blockDim.x + threadIdx.x;
    if (e >= EE) return;
    int a = ei[e], b = ei[EE + e];
    int pb = g_rowptr[b] + atomicAdd(&g_cursor[b], 1);
    g_col[pb] = a;
    int pa = g_rowptr[a] + atomicAdd(&g_cursor[a], 1);
    g_col[pa] = b;
}

// ---------------- gather-side mean aggregation: warp per node ----------------
template<int LAYER>
__global__ void __launch_bounds__(256) aggregate_kernel(
    const float* __restrict__ xin) {
    const float* feat = (LAYER == 0) ? xin : g_h1;
    int node = (int)((blockIdx.x * blockDim.x + threadIdx.x) >> 5);
    if (node >= NN) return;
    int lane = threadIdx.x & 31;
    int c = lane * 4;

    float4 acc = *(const float4*)(feat + (size_t)node * DD + c);  // self loop
    int s = g_rowptr[node];
    int e = g_rowptr[node + 1];

    int j = s;
    for (; j + 4 <= e; j += 4) {
        int n0 = g_col[j + 0], n1 = g_col[j + 1];
        int n2 = g_col[j + 2], n3 = g_col[j + 3];
        float4 v0 = *(const float4*)(feat + (size_t)n0 * DD + c);
        float4 v1 = *(const float4*)(feat + (size_t)n1 * DD + c);
        float4 v2 = *(const float4*)(feat + (size_t)n2 * DD + c);
        float4 v3 = *(const float4*)(feat + (size_t)n3 * DD + c);
        acc.x += v0.x + v1.x + v2.x + v3.x;
        acc.y += v0.y + v1.y + v2.y + v3.y;
        acc.z += v0.z + v1.z + v2.z + v3.z;
        acc.w += v0.w + v1.w + v2.w + v3.w;
    }
    for (; j < e; j++) {
        int nb = g_col[j];
        float4 v = *(const float4*)(feat + (size_t)nb * DD + c);
        acc.x += v.x; acc.y += v.y; acc.z += v.z; acc.w += v.w;
    }

    float inv = 1.0f / (float)(e - s + 1);
    acc.x *= inv; acc.y *= inv; acc.z *= inv; acc.w *= inv;
    *(float4*)(g_agg + (size_t)node * DD + c) = acc;
}

// ---------------- fused dual GEMM, 8 nodes/warp register tiling --------------
// hpre = A@Wa^T + agg@Wb^T + bias. 512 thr, 128-node tile, K split in halves
// (self-part then agg-part) reusing one 64KB input buffer; acc in registers.
template<int LAYER>
__global__ void __launch_bounds__(512, 1) gemm_dual_kernel(
    const float* __restrict__ xin,
    const float* __restrict__ Wa, const float* __restrict__ Wb,
    const float* __restrict__ ba, const float* __restrict__ bb) {
    extern __shared__ float sm[];
    float* sW  = sm;                 // 256 rows x 128 (transposed weights)
    float* sIn = sm + 256 * DD;      // 128 nodes x 128
    const float* A = (LAYER == 0) ? xin : g_h1;
    const float* B = g_agg;
    int tid = threadIdx.x;

    for (int i = tid; i < DD * DD; i += 512) {
        int f = i >> 7, k = i & 127;
        sW[k * DD + f]        = Wa[i];
        sW[(k + DD) * DD + f] = Wb[i];
    }

    int warp = tid >> 5, lane = tid & 31;
    int f0 = lane * 4;
    float bs0 = ba[f0 + 0] + bb[f0 + 0];
    float bs1 = ba[f0 + 1] + bb[f0 + 1];
    float bs2 = ba[f0 + 2] + bb[f0 + 2];
    float bs3 = ba[f0 + 3] + bb[f0 + 3];
    float cs0 = 0.f, cs1 = 0.f, cs2 = 0.f, cs3 = 0.f;
    float cq0 = 0.f, cq1 = 0.f, cq2 = 0.f, cq3 = 0.f;

    const float* inp = sIn + (warp * 8) * DD;   // this warp's 8 node rows
    const int NT = (NN + 127) / 128;

    for (int tile = blockIdx.x; tile < NT; tile += gridDim.x) {
        int base = tile * 128;
        float acc[8][4];
        #pragma unroll
        for (int n = 0; n < 8; n++)
            #pragma unroll
            for (int c4 = 0; c4 < 4; c4++) acc[n][c4] = 0.f;

        #pragma unroll
        for (int half = 0; half < 2; half++) {
            const float* src = (half == 0) ? A : B;
            const float* ws  = sW + half * DD * DD;
            __syncthreads();   // previous contents consumed (covers sW 1st use)
            for (int i = tid; i < 128 * 32; i += 512) {
                int n = i >> 5, q = i & 31;
                int node = base + n;
                float4 v = make_float4(0.f, 0.f, 0.f, 0.f);
                if (node < NN)
                    v = *(const float4*)(src + (size_t)node * DD + q * 4);
                *(float4*)(sIn + n * DD + q * 4) = v;
            }
            __syncthreads();

            for (int k = 0; k < DD; k += 4) {
                float4 w0 = *(const float4*)(ws + (k + 0) * DD + f0);
                float4 w1 = *(const float4*)(ws + (k + 1) * DD + f0);
                float4 w2 = *(const float4*)(ws + (k + 2) * DD + f0);
                float4 w3 = *(const float4*)(ws + (k + 3) * DD + f0);
                #pragma unroll
                for (int n = 0; n < 8; n++) {
                    float4 v = *(const float4*)(inp + n * DD + k);
                    acc[n][0] += w0.x * v.x; acc[n][1] += w0.y * v.x;
                    acc[n][2] += w0.z * v.x; acc[n][3] += w0.w * v.x;
                    acc[n][0] += w1.x * v.y; acc[n][1] += w1.y * v.y;
                    acc[n][2] += w1.z * v.y; acc[n][3] += w1.w * v.y;
                    acc[n][0] += w2.x * v.z; acc[n][1] += w2.y * v.z;
                    acc[n][2] += w2.z * v.z; acc[n][3] += w2.w * v.z;
                    acc[n][0] += w3.x * v.w; acc[n][1] += w3.y * v.w;
                    acc[n][2] += w3.z * v.w; acc[n][3] += w3.w * v.w;
                }
            }
        }

        #pragma unroll
        for (int n = 0; n < 8; n++) {
            int node = base + warp * 8 + n;
            if (node < NN) {
                float o0 = acc[n][0] + bs0;
                float o1 = acc[n][1] + bs1;
                float o2 = acc[n][2] + bs2;
                float o3 = acc[n][3] + bs3;
                *(float4*)(g_hpre + (size_t)node * DD + f0) =
                    make_float4(o0, o1, o2, o3);
                cs0 += o0; cq0 += o0 * o0;
                cs1 += o1; cq1 += o1 * o1;
                cs2 += o2; cq2 += o2 * o2;
                cs3 += o3; cq3 += o3 * o3;
            }
        }
    }

    atomicAdd(&g_colsum[f0 + 0], cs0); atomicAdd(&g_colsq[f0 + 0], cq0);
    atomicAdd(&g_colsum[f0 + 1], cs1); atomicAdd(&g_colsq[f0 + 1], cq1);
    atomicAdd(&g_colsum[f0 + 2], cs2); atomicAdd(&g_colsq[f0 + 2], cq2);
    atomicAdd(&g_colsum[f0 + 3], cs3); atomicAdd(&g_colsq[f0 + 3], cq3);
}

// ---------------- BN finalize: stats -> scale/shift, reset stats ------------
__global__ void bn_finalize_kernel(const float* __restrict__ gamma,
                                   const float* __restrict__ beta) {
    int c = threadIdx.x;
    float mean = g_colsum[c] * (1.0f / NN);
    float var  = g_colsq[c]  * (1.0f / NN) - mean * mean;
    float sc   = gamma[c] * rsqrtf(var + 1e-5f);
    g_scale[c] = sc;
    g_shift[c] = beta[c] - mean * sc;
    g_colsum[c] = 0.f;
    g_colsq[c]  = 0.f;
}

// ---------------- apply BN+ReLU -> g_h1 -------------------------------------
__global__ void apply_bn_kernel() {
    int idx = blockIdx.x * blockDim.x + threadIdx.x;
    if (idx >= NN * 32) return;
    int q = idx & 31;
    float4 v  = ((const float4*)g_hpre)[idx];
    float4 sc = *(const float4*)(g_scale + q * 4);
    float4 sh = *(const float4*)(g_shift + q * 4);
    v.x = fmaxf(v.x * sc.x + sh.x, 0.f);
    v.y = fmaxf(v.y * sc.y + sh.y, 0.f);
    v.z = fmaxf(v.z * sc.z + sh.z, 0.f);
    v.w = fmaxf(v.w * sc.w + sh.w, 0.f);
    ((float4*)g_h1)[idx] = v;
}

// ---------------- head: out = relu(bn(hpre)) @ Wh^T + bh  (fused BN) --------
__global__ void __launch_bounds__(512, 2) head_kernel(
    const float* __restrict__ Wh, const float* __restrict__ bh,
    float* __restrict__ outp) {
    extern __shared__ float sm[];
    float* sW  = sm;              // 128 rows x HPAD
    float* sIn = sm + DD * HPAD;  // 64 nodes x 128
    int tid = threadIdx.x;

    for (int i = tid; i < 64 * DD; i += 512) {
        int f = i >> 7, k = i & 127;
        sW[k * HPAD + f] = Wh[i];
    }

    int base = blockIdx.x * 64;
    for (int i = tid; i < 64 * 32; i += 512) {
        int n = i >> 5, q = i & 31;
        int node = base + n;
        float4 v = make_float4(0.f, 0.f, 0.f, 0.f);
        if (node < NN) {
            v = ((const float4*)(g_hpre + (size_t)node * DD))[q];
            float4 sc = *(const float4*)(g_scale + q * 4);
            float4 sh = *(const float4*)(g_shift + q * 4);
            v.x = fmaxf(v.x * sc.x + sh.x, 0.f);
            v.y = fmaxf(v.y * sc.y + sh.y, 0.f);
            v.z = fmaxf(v.z * sc.z + sh.z, 0.f);
            v.w = fmaxf(v.w * sc.w + sh.w, 0.f);
        }
        *(float4*)(sIn + n * DD + q * 4) = v;
    }
    __syncthreads();

    int warp = tid >> 5, lane = tid & 31;
    int f0 = lane * 2;
    float b0 = bh[f0], b1 = bh[f0 + 1];
    float acc[4][2];
    #pragma unroll
    for (int i = 0; i < 4; i++) { acc[i][0] = 0.f; acc[i][1] = 0.f; }

    const float* in0 = sIn + (warp * 4 + 0) * DD;
    const float* in1 = sIn + (warp * 4 + 1) * DD;
    const float* in2 = sIn + (warp * 4 + 2) * DD;
    const float* in3 = sIn + (warp * 4 + 3) * DD;

    for (int k = 0; k < DD; k += 4) {
        float4 v0 = *(const float4*)(in0 + k);
        float4 v1 = *(const float4*)(in1 + k);
        float4 v2 = *(const float4*)(in2 + k);
        float4 v3 = *(const float4*)(in3 + k);
        #pragma unroll
        for (int kk = 0; kk < 4; kk++) {
            float2 wv = *(const float2*)(sW + (k + kk) * HPAD + f0);
            float e;
            e = ((const float*)&v0)[kk]; acc[0][0] += wv.x * e; acc[0][1] += wv.y * e;
            e = ((const float*)&v1)[kk]; acc[1][0] += wv.x * e; acc[1][1] += wv.y * e;
            e = ((const float*)&v2)[kk]; acc[2][0] += wv.x * e; acc[2][1] += wv.y * e;
            e = ((const float*)&v3)[kk]; acc[3][0] += wv.x * e; acc[3][1] += wv.y * e;
        }
    }

    #pragma unroll
    for (int nidx = 0; nidx < 4; nidx++) {
        int node = base + warp * 4 + nidx;
        if (node < NN) {
            float2 o = make_float2(acc[nidx][0] + b0, acc[nidx][1] + b1);
            *(float2*)(outp + (size_t)node * 64 + f0) = o;
        }
    }
}

// ---------------- launch ----------------------------------------------------
extern "C" void kernel_launch(void* const* d_in, const int* in_sizes, int n_in,
                              void* d_out, int out_size) {
    const float* x   = (const float*)d_in[0];
    const int*   ei  = (const int*)d_in[1];     // int32 (JAX default int)
    const float* Ws1 = (const float*)d_in[2];
    const float* bs1 = (const float*)d_in[3];
    const float* Wn1 = (const float*)d_in[4];
    const float* bn1 = (const float*)d_in[5];
    const float* g1  = (const float*)d_in[6];
    const float* be1 = (const float*)d_in[7];
    const float* Ws2 = (const float*)d_in[8];
    const float* bs2 = (const float*)d_in[9];
    const float* Wn2 = (const float*)d_in[10];
    const float* bn2 = (const float*)d_in[11];
    const float* g2  = (const float*)d_in[12];
    const float* be2 = (const float*)d_in[13];
    const float* Wh  = (const float*)d_in[14];
    const float* bh  = (const float*)d_in[15];
    float* out = (float*)d_out;

    const int GEMM_SMEM = (256 * DD + 128 * DD) * 4;     // 196608 B
    const int HEAD_SMEM = (DD * HPAD + 64 * DD) * 4;     // 66560 B
    cudaFuncSetAttribute(gemm_dual_kernel<0>,
                         cudaFuncAttributeMaxDynamicSharedMemorySize, GEMM_SMEM);
    cudaFuncSetAttribute(gemm_dual_kernel<1>,
                         cudaFuncAttributeMaxDynamicSharedMemorySize, GEMM_SMEM);
    cudaFuncSetAttribute(head_kernel,
                         cudaFuncAttributeMaxDynamicSharedMemorySize, HEAD_SMEM);

    // CSR build (once; reused by both layers)
    zero_kernel<<<(NN + 255) / 256, 256>>>();
    count_kernel<<<(EE + 255) / 256, 256>>>(ei);
    scan_kernel<<<1, 1024>>>();
    scatter_kernel<<<(EE + 255) / 256, 256>>>(ei);

    // layer 1
    aggregate_kernel<0><<<(NN * 32 + 255) / 256, 256>>>(x);
    gemm_dual_kernel<0><<<148, 512, GEMM_SMEM>>>(x, Ws1, Wn1, bs1, bn1);
    bn_finalize_kernel<<<1, 128>>>(g1, be1);
    apply_bn_kernel<<<(NN * 32 + 255) / 256, 256>>>();

    // layer 2
    aggregate_kernel<1><<<(NN * 32 + 255) / 256, 256>>>(x);
    gemm_dual_kernel<1><<<148, 512, GEMM_SMEM>>>(x, Ws2, Wn2, bs2, bn2);
    bn_finalize_kernel<<<1, 128>>>(g2, be2);

    // head
    head_kernel<<<(NN + 63) / 64, 512, HEAD_SMEM>>>(Wh, bh, out);
}

// round 9
// speedup vs baseline: 4.1221x; 1.5843x over previous
#include <cuda_runtime.h>
#include <cstdint>

#define NN 100000
#define DD 128
#define EE 1600000
#define SP 132     // padded smem row stride (floats) for mma staging
#define HPAD 66    // padded row stride for 128x64 transposed head weights

// ---------------- scratch (device globals; no allocations allowed) ----------
__device__ __align__(16) float g_agg [(size_t)NN * DD];  // normalized aggregation
__device__ __align__(16) float g_hpre[(size_t)NN * DD];  // pre-BN activations
__device__ __align__(16) float g_h1  [(size_t)NN * DD];  // post-BN/ReLU layer-1
__device__ int   g_deg   [NN];
__device__ int   g_cursor[NN];
__device__ int   g_rowptr[NN + 1];
__device__ int   g_col   [2 * EE];
__device__ float g_colsum[DD];
__device__ float g_colsq [DD];
__device__ __align__(16) float g_scale[DD];
__device__ __align__(16) float g_shift[DD];

// ---------------- CSR build --------------------------------------------------
__global__ void zero_kernel() {
    int i = blockIdx.x * blockDim.x + threadIdx.x;
    if (i < NN) { g_deg[i] = 0; g_cursor[i] = 0; }
    if (i < DD) { g_colsum[i] = 0.f; g_colsq[i] = 0.f; }
}

__global__ void count_kernel(const int* __restrict__ ei) {
    int e = blockIdx.x * blockDim.x + threadIdx.x;
    if (e >= EE) return;
    int a = ei[e], b = ei[EE + e];
    atomicAdd(&g_deg[a], 1);
    atomicAdd(&g_deg[b], 1);
}

// single-block scan over g_deg -> g_rowptr
__global__ void scan_kernel() {
    __shared__ int warp_sums[32];
    int tid = threadIdx.x;            // 1024 threads
    int lane = tid & 31, wid = tid >> 5;
    int running = 0;
    for (int base = 0; base < NN; base += 1024) {
        int i = base + tid;
        int v = (i < NN) ? g_deg[i] : 0;
        int x = v;
        #pragma unroll
        for (int o = 1; o < 32; o <<= 1) {
            int y = __shfl_up_sync(0xffffffffu, x, o);
            if (lane >= o) x += y;
        }
        if (lane == 31) warp_sums[wid] = x;
        __syncthreads();
        if (wid == 0) {
            int s = warp_sums[lane];
            #pragma unroll
            for (int o = 1; o < 32; o <<= 1) {
                int y = __shfl_up_sync(0xffffffffu, s, o);
                if (lane >= o) s += y;
            }
            warp_sums[lane] = s;
        }
        __syncthreads();
        int incl = running + (wid > 0 ? warp_sums[wid - 1] : 0) + x;
        if (i < NN) g_rowptr[i + 1] = incl;
        running += warp_sums[31];
        __syncthreads();
    }
    if (tid == 0) g_rowptr[0] = 0;
}

__global__ void scatter_kernel(const int* __restrict__ ei) {
    int e = blockIdx.x * blockDim.x + threadIdx.x;
    if (e >= EE) return;
    int a = ei[e], b = ei[EE + e];
    int pb = g_rowptr[b] + atomicAdd(&g_cursor[b], 1);
    g_col[pb] = a;
    int pa = g_rowptr[a] + atomicAdd(&g_cursor[a], 1);
    g_col[pa] = b;
}

// ---------------- gather-side mean aggregation: warp per node ----------------
template<int LAYER>
__global__ void __launch_bounds__(256) aggregate_kernel(
    const float* __restrict__ xin) {
    const float* feat = (LAYER == 0) ? xin : g_h1;
    int node = (int)((blockIdx.x * blockDim.x + threadIdx.x) >> 5);
    if (node >= NN) return;
    int lane = threadIdx.x & 31;
    int c = lane * 4;

    float4 acc = *(const float4*)(feat + (size_t)node * DD + c);  // self loop
    int s = g_rowptr[node];
    int e = g_rowptr[node + 1];

    int j = s;
    for (; j + 4 <= e; j += 4) {
        int n0 = g_col[j + 0], n1 = g_col[j + 1];
        int n2 = g_col[j + 2], n3 = g_col[j + 3];
        float4 v0 = *(const float4*)(feat + (size_t)n0 * DD + c);
        float4 v1 = *(const float4*)(feat + (size_t)n1 * DD + c);
        float4 v2 = *(const float4*)(feat + (size_t)n2 * DD + c);
        float4 v3 = *(const float4*)(feat + (size_t)n3 * DD + c);
        acc.x += v0.x + v1.x + v2.x + v3.x;
        acc.y += v0.y + v1.y + v2.y + v3.y;
        acc.z += v0.z + v1.z + v2.z + v3.z;
        acc.w += v0.w + v1.w + v2.w + v3.w;
    }
    for (; j < e; j++) {
        int nb = g_col[j];
        float4 v = *(const float4*)(feat + (size_t)nb * DD + c);
        acc.x += v.x; acc.y += v.y; acc.z += v.z; acc.w += v.w;
    }

    float inv = 1.0f / (float)(e - s + 1);
    acc.x *= inv; acc.y *= inv; acc.z *= inv; acc.w *= inv;
    *(float4*)(g_agg + (size_t)node * DD + c) = acc;
}

// ---------------- TF32 helpers ----------------------------------------------
__device__ __forceinline__ uint32_t f2tf32(float x) {
    uint32_t r;
    asm("cvt.rna.tf32.f32 %0, %1;" : "=r"(r) : "f"(x));
    return r;
}

__device__ __forceinline__ void mma_tf32(float* c, const uint32_t* a,
                                         const uint32_t* b) {
    asm volatile(
        "mma.sync.aligned.m16n8k8.row.col.f32.tf32.tf32.f32 "
        "{%0,%1,%2,%3}, {%4,%5,%6,%7}, {%8,%9}, {%0,%1,%2,%3};\n"
        : "+f"(c[0]), "+f"(c[1]), "+f"(c[2]), "+f"(c[3])
        : "r"(a[0]), "r"(a[1]), "r"(a[2]), "r"(a[3]), "r"(b[0]), "r"(b[1]));
}

// ---------------- fused dual GEMM via TF32 mma.sync --------------------------
// hpre = A@Wa^T + agg@Wb^T + bias.  512 thr = 16 warps (4x4), each warp 32x32
// output; K=256 split in two 128-halves (self then agg) reusing one stage buf.
template<int LAYER>
__global__ void __launch_bounds__(512, 1) gemm_dual_kernel(
    const float* __restrict__ xin,
    const float* __restrict__ Wa, const float* __restrict__ Wb,
    const float* __restrict__ ba, const float* __restrict__ bb) {
    extern __shared__ float sm[];
    float* sW    = sm;                   // 256 x SP (tf32 bits, [k][f])
    float* sIn   = sm + 256 * SP;        // 128 x SP (tf32 bits, [node][k])
    float* sBias = sIn + 128 * SP;       // 128
    const float* A = (LAYER == 0) ? xin : g_h1;
    const float* B = g_agg;
    int tid = threadIdx.x;

    for (int i = tid; i < DD * DD; i += 512) {
        int f = i >> 7, k = i & 127;
        sW[k * SP + f]        = __uint_as_float(f2tf32(Wa[i]));
        sW[(k + DD) * SP + f] = __uint_as_float(f2tf32(Wb[i]));
    }
    if (tid < DD) sBias[tid] = ba[tid] + bb[tid];

    int warp = tid >> 5, lane = tid & 31;
    int warpM = warp & 3, warpN = warp >> 2;      // 4x4 warp grid
    int g = lane >> 2, t = lane & 3;
    int cb = warpN * 32;                          // warp's col base

    float csum[4][2], csq[4][2];                  // BN partials (persist)
    #pragma unroll
    for (int n = 0; n < 4; n++) {
        csum[n][0] = csum[n][1] = 0.f;
        csq[n][0]  = csq[n][1]  = 0.f;
    }

    const int NT = (NN + 127) / 128;
    for (int tile = blockIdx.x; tile < NT; tile += gridDim.x) {
        int base = tile * 128;
        float C[2][4][4];
        #pragma unroll
        for (int m = 0; m < 2; m++)
            #pragma unroll
            for (int n = 0; n < 4; n++)
                #pragma unroll
                for (int r = 0; r < 4; r++) C[m][n][r] = 0.f;

        #pragma unroll
        for (int half = 0; half < 2; half++) {
            const float* src = (half == 0) ? A : B;
            const float* ws  = sW + half * DD * SP;
            __syncthreads();   // prior consumers done (covers sW/sBias 1st use)
            for (int i = tid; i < 128 * 32; i += 512) {
                int n = i >> 5, q = i & 31;
                int node = base + n;
                float4 v = make_float4(0.f, 0.f, 0.f, 0.f);
                if (node < NN)
                    v = *(const float4*)(src + (size_t)node * DD + q * 4);
                float4 o;
                o.x = __uint_as_float(f2tf32(v.x));
                o.y = __uint_as_float(f2tf32(v.y));
                o.z = __uint_as_float(f2tf32(v.z));
                o.w = __uint_as_float(f2tf32(v.w));
                *(float4*)(sIn + n * SP + q * 4) = o;
            }
            __syncthreads();

            #pragma unroll
            for (int kk = 0; kk < 16; kk++) {
                int k = kk * 8;
                uint32_t a[2][4];
                #pragma unroll
                for (int m = 0; m < 2; m++) {
                    const float* ap =
                        sIn + (warpM * 32 + m * 16 + g) * SP + k + t;
                    a[m][0] = __float_as_uint(ap[0]);
                    a[m][1] = __float_as_uint(ap[8 * SP]);
                    a[m][2] = __float_as_uint(ap[4]);
                    a[m][3] = __float_as_uint(ap[8 * SP + 4]);
                }
                uint32_t b[4][2];
                #pragma unroll
                for (int n = 0; n < 4; n++) {
                    const float* bp = ws + (k + t) * SP + cb + n * 8 + g;
                    b[n][0] = __float_as_uint(bp[0]);
                    b[n][1] = __float_as_uint(bp[4 * SP]);
                }
                #pragma unroll
                for (int m = 0; m < 2; m++)
                    #pragma unroll
                    for (int n = 0; n < 4; n++)
                        mma_tf32(C[m][n], a[m], b[n]);
            }
        }

        // epilogue: bias add, store, BN partials (only valid rows)
        #pragma unroll
        for (int m = 0; m < 2; m++) {
            int r0 = base + warpM * 32 + m * 16 + g;
            int r1 = r0 + 8;
            #pragma unroll
            for (int n = 0; n < 4; n++) {
                int col = cb + n * 8 + 2 * t;
                float b0v = sBias[col], b1v = sBias[col + 1];
                float v0 = C[m][n][0] + b0v, v1 = C[m][n][1] + b1v;
                float v2 = C[m][n][2] + b0v, v3 = C[m][n][3] + b1v;
                if (r0 < NN) {
                    *(float2*)(g_hpre + (size_t)r0 * DD + col) =
                        make_float2(v0, v1);
                    csum[n][0] += v0; csq[n][0] += v0 * v0;
                    csum[n][1] += v1; csq[n][1] += v1 * v1;
                }
                if (r1 < NN) {
                    *(float2*)(g_hpre + (size_t)r1 * DD + col) =
                        make_float2(v2, v3);
                    csum[n][0] += v2; csq[n][0] += v2 * v2;
                    csum[n][1] += v3; csq[n][1] += v3 * v3;
                }
            }
        }
    }

    // shfl-reduce BN partials over g (lanes sharing a column), then atomics
    #pragma unroll
    for (int n = 0; n < 4; n++)
        #pragma unroll
        for (int c = 0; c < 2; c++) {
            float s = csum[n][c], q = csq[n][c];
            #pragma unroll
            for (int o = 4; o < 32; o <<= 1) {
                s += __shfl_xor_sync(0xffffffffu, s, o);
                q += __shfl_xor_sync(0xffffffffu, q, o);
            }
            if (g == 0) {
                int col = cb + n * 8 + 2 * t + c;
                atomicAdd(&g_colsum[col], s);
                atomicAdd(&g_colsq[col], q);
            }
        }
}

// ---------------- BN finalize: stats -> scale/shift, reset stats ------------
__global__ void bn_finalize_kernel(const float* __restrict__ gamma,
                                   const float* __restrict__ beta) {
    int c = threadIdx.x;
    float mean = g_colsum[c] * (1.0f / NN);
    float var  = g_colsq[c]  * (1.0f / NN) - mean * mean;
    float sc   = gamma[c] * rsqrtf(var + 1e-5f);
    g_scale[c] = sc;
    g_shift[c] = beta[c] - mean * sc;
    g_colsum[c] = 0.f;
    g_colsq[c]  = 0.f;
}

// ---------------- apply BN+ReLU -> g_h1 -------------------------------------
__global__ void apply_bn_kernel() {
    int idx = blockIdx.x * blockDim.x + threadIdx.x;
    if (idx >= NN * 32) return;
    int q = idx & 31;
    float4 v  = ((const float4*)g_hpre)[idx];
    float4 sc = *(const float4*)(g_scale + q * 4);
    float4 sh = *(const float4*)(g_shift + q * 4);
    v.x = fmaxf(v.x * sc.x + sh.x, 0.f);
    v.y = fmaxf(v.y * sc.y + sh.y, 0.f);
    v.z = fmaxf(v.z * sc.z + sh.z, 0.f);
    v.w = fmaxf(v.w * sc.w + sh.w, 0.f);
    ((float4*)g_h1)[idx] = v;
}

// ---------------- head: out = relu(bn(hpre)) @ Wh^T + bh  (fused BN) --------
__global__ void __launch_bounds__(512, 2) head_kernel(
    const float* __restrict__ Wh, const float* __restrict__ bh,
    float* __restrict__ outp) {
    extern __shared__ float sm[];
    float* sW  = sm;              // 128 rows x HPAD
    float* sIn = sm + DD * HPAD;  // 64 nodes x 128
    int tid = threadIdx.x;

    for (int i = tid; i < 64 * DD; i += 512) {
        int f = i >> 7, k = i & 127;
        sW[k * HPAD + f] = Wh[i];
    }

    int base = blockIdx.x * 64;
    for (int i = tid; i < 64 * 32; i += 512) {
        int n = i >> 5, q = i & 31;
        int node = base + n;
        float4 v = make_float4(0.f, 0.f, 0.f, 0.f);
        if (node < NN) {
            v = ((const float4*)(g_hpre + (size_t)node * DD))[q];
            float4 sc = *(const float4*)(g_scale + q * 4);
            float4 sh = *(const float4*)(g_shift + q * 4);
            v.x = fmaxf(v.x * sc.x + sh.x, 0.f);
            v.y = fmaxf(v.y * sc.y + sh.y, 0.f);
            v.z = fmaxf(v.z * sc.z + sh.z, 0.f);
            v.w = fmaxf(v.w * sc.w + sh.w, 0.f);
        }
        *(float4*)(sIn + n * DD + q * 4) = v;
    }
    __syncthreads();

    int warp = tid >> 5, lane = tid & 31;
    int f0 = lane * 2;
    float b0 = bh[f0], b1 = bh[f0 + 1];
    float acc[4][2];
    #pragma unroll
    for (int i = 0; i < 4; i++) { acc[i][0] = 0.f; acc[i][1] = 0.f; }

    const float* in0 = sIn + (warp * 4 + 0) * DD;
    const float* in1 = sIn + (warp * 4 + 1) * DD;
    const float* in2 = sIn + (warp * 4 + 2) * DD;
    const float* in3 = sIn + (warp * 4 + 3) * DD;

    for (int k = 0; k < DD; k += 4) {
        float4 v0 = *(const float4*)(in0 + k);
        float4 v1 = *(const float4*)(in1 + k);
        float4 v2 = *(const float4*)(in2 + k);
        float4 v3 = *(const float4*)(in3 + k);
        #pragma unroll
        for (int kk = 0; kk < 4; kk++) {
            float2 wv = *(const float2*)(sW + (k + kk) * HPAD + f0);
            float e;
            e = ((const float*)&v0)[kk]; acc[0][0] += wv.x * e; acc[0][1] += wv.y * e;
            e = ((const float*)&v1)[kk]; acc[1][0] += wv.x * e; acc[1][1] += wv.y * e;
            e = ((const float*)&v2)[kk]; acc[2][0] += wv.x * e; acc[2][1] += wv.y * e;
            e = ((const float*)&v3)[kk]; acc[3][0] += wv.x * e; acc[3][1] += wv.y * e;
        }
    }

    #pragma unroll
    for (int nidx = 0; nidx < 4; nidx++) {
        int node = base + warp * 4 + nidx;
        if (node < NN) {
            float2 o = make_float2(acc[nidx][0] + b0, acc[nidx][1] + b1);
            *(float2*)(outp + (size_t)node * 64 + f0) = o;
        }
    }
}

// ---------------- launch ----------------------------------------------------
extern "C" void kernel_launch(void* const* d_in, const int* in_sizes, int n_in,
                              void* d_out, int out_size) {
    const float* x   = (const float*)d_in[0];
    const int*   ei  = (const int*)d_in[1];     // int32 (JAX default int)
    const float* Ws1 = (const float*)d_in[2];
    const float* bs1 = (const float*)d_in[3];
    const float* Wn1 = (const float*)d_in[4];
    const float* bn1 = (const float*)d_in[5];
    const float* g1  = (const float*)d_in[6];
    const float* be1 = (const float*)d_in[7];
    const float* Ws2 = (const float*)d_in[8];
    const float* bs2 = (const float*)d_in[9];
    const float* Wn2 = (const float*)d_in[10];
    const float* bn2 = (const float*)d_in[11];
    const float* g2  = (const float*)d_in[12];
    const float* be2 = (const float*)d_in[13];
    const float* Wh  = (const float*)d_in[14];
    const float* bh  = (const float*)d_in[15];
    float* out = (float*)d_out;

    const int GEMM_SMEM = (256 * SP + 128 * SP + 128) * 4;   // 203264 B
    const int HEAD_SMEM = (DD * HPAD + 64 * DD) * 4;         // 66560 B
    cudaFuncSetAttribute(gemm_dual_kernel<0>,
                         cudaFuncAttributeMaxDynamicSharedMemorySize, GEMM_SMEM);
    cudaFuncSetAttribute(gemm_dual_kernel<1>,
                         cudaFuncAttributeMaxDynamicSharedMemorySize, GEMM_SMEM);
    cudaFuncSetAttribute(head_kernel,
                         cudaFuncAttributeMaxDynamicSharedMemorySize, HEAD_SMEM);

    // CSR build (once; reused by both layers)
    zero_kernel<<<(NN + 255) / 256, 256>>>();
    count_kernel<<<(EE + 255) / 256, 256>>>(ei);
    scan_kernel<<<1, 1024>>>();
    scatter_kernel<<<(EE + 255) / 256, 256>>>(ei);

    // layer 1
    aggregate_kernel<0><<<(NN * 32 + 255) / 256, 256>>>(x);
    gemm_dual_kernel<0><<<148, 512, GEMM_SMEM>>>(x, Ws1, Wn1, bs1, bn1);
    bn_finalize_kernel<<<1, 128>>>(g1, be1);
    apply_bn_kernel<<<(NN * 32 + 255) / 256, 256>>>();

    // layer 2
    aggregate_kernel<1><<<(NN * 32 + 255) / 256, 256>>>(x);
    gemm_dual_kernel<1><<<148, 512, GEMM_SMEM>>>(x, Ws2, Wn2, bs2, bn2);
    bn_finalize_kernel<<<1, 128>>>(g2, be2);

    // head
    head_kernel<<<(NN + 63) / 64, 512, HEAD_SMEM>>>(Wh, bh, out);
}

// round 10
// speedup vs baseline: 4.3657x; 1.0591x over previous
#include <cuda_runtime.h>
#include <cstdint>

#define NN 100000
#define DD 128
#define EE 1600000
#define SP 132     // padded smem row stride (floats) for mma staging
#define SP2 68     // padded stride for head weight rows (64 cols)

// ---------------- scratch (device globals; no allocations allowed) ----------
__device__ __align__(16) float g_agg [(size_t)NN * DD];  // normalized aggregation
__device__ __align__(16) float g_hpre[(size_t)NN * DD];  // pre-BN activations
__device__ int   g_deg   [NN];
__device__ int   g_cursor[NN];
__device__ int   g_rowptr[NN + 1];
__device__ int   g_col   [2 * EE];
__device__ float g_colsum[DD];
__device__ float g_colsq [DD];
__device__ __align__(16) float g_scale[DD];
__device__ __align__(16) float g_shift[DD];

// ---------------- CSR build --------------------------------------------------
__global__ void zero_kernel() {
    int i = blockIdx.x * blockDim.x + threadIdx.x;
    if (i < NN) { g_deg[i] = 0; g_cursor[i] = 0; }
    if (i < DD) { g_colsum[i] = 0.f; g_colsq[i] = 0.f; }
}

__global__ void count_kernel(const int* __restrict__ ei) {
    int e = blockIdx.x * blockDim.x + threadIdx.x;
    if (e >= EE) return;
    int a = ei[e], b = ei[EE + e];
    atomicAdd(&g_deg[a], 1);
    atomicAdd(&g_deg[b], 1);
}

// single-block scan over g_deg -> g_rowptr
__global__ void scan_kernel() {
    __shared__ int warp_sums[32];
    int tid = threadIdx.x;            // 1024 threads
    int lane = tid & 31, wid = tid >> 5;
    int running = 0;
    for (int base = 0; base < NN; base += 1024) {
        int i = base + tid;
        int v = (i < NN) ? g_deg[i] : 0;
        int x = v;
        #pragma unroll
        for (int o = 1; o < 32; o <<= 1) {
            int y = __shfl_up_sync(0xffffffffu, x, o);
            if (lane >= o) x += y;
        }
        if (lane == 31) warp_sums[wid] = x;
        __syncthreads();
        if (wid == 0) {
            int s = warp_sums[lane];
            #pragma unroll
            for (int o = 1; o < 32; o <<= 1) {
                int y = __shfl_up_sync(0xffffffffu, s, o);
                if (lane >= o) s += y;
            }
            warp_sums[lane] = s;
        }
        __syncthreads();
        int incl = running + (wid > 0 ? warp_sums[wid - 1] : 0) + x;
        if (i < NN) g_rowptr[i + 1] = incl;
        running += warp_sums[31];
        __syncthreads();
    }
    if (tid == 0) g_rowptr[0] = 0;
}

__global__ void scatter_kernel(const int* __restrict__ ei) {
    int e = blockIdx.x * blockDim.x + threadIdx.x;
    if (e >= EE) return;
    int a = ei[e], b = ei[EE + e];
    int pb = g_rowptr[b] + atomicAdd(&g_cursor[b], 1);
    g_col[pb] = a;
    int pa = g_rowptr[a] + atomicAdd(&g_cursor[a], 1);
    g_col[pa] = b;
}

// ---------------- gather-side mean aggregation: warp per node ----------------
// LAYER 0: feat = x (plain). LAYER 1: feat = relu(bn(g_hpre)) applied on the fly.
template<int LAYER>
__global__ void __launch_bounds__(256) aggregate_kernel(
    const float* __restrict__ xin) {
    const float* feat = (LAYER == 0) ? xin : g_hpre;
    int node = (int)((blockIdx.x * blockDim.x + threadIdx.x) >> 5);
    if (node >= NN) return;
    int lane = threadIdx.x & 31;
    int c = lane * 4;

    float4 sc = make_float4(1.f, 1.f, 1.f, 1.f);
    float4 sh = make_float4(0.f, 0.f, 0.f, 0.f);
    if (LAYER == 1) {
        sc = *(const float4*)(g_scale + c);
        sh = *(const float4*)(g_shift + c);
    }

    float4 acc = *(const float4*)(feat + (size_t)node * DD + c);  // self loop
    if (LAYER == 1) {
        acc.x = fmaxf(acc.x * sc.x + sh.x, 0.f);
        acc.y = fmaxf(acc.y * sc.y + sh.y, 0.f);
        acc.z = fmaxf(acc.z * sc.z + sh.z, 0.f);
        acc.w = fmaxf(acc.w * sc.w + sh.w, 0.f);
    }
    int s = g_rowptr[node];
    int e = g_rowptr[node + 1];

    int j = s;
    for (; j + 4 <= e; j += 4) {
        int n0 = g_col[j + 0], n1 = g_col[j + 1];
        int n2 = g_col[j + 2], n3 = g_col[j + 3];
        float4 v0 = *(const float4*)(feat + (size_t)n0 * DD + c);
        float4 v1 = *(const float4*)(feat + (size_t)n1 * DD + c);
        float4 v2 = *(const float4*)(feat + (size_t)n2 * DD + c);
        float4 v3 = *(const float4*)(feat + (size_t)n3 * DD + c);
        if (LAYER == 1) {
            v0.x = fmaxf(v0.x * sc.x + sh.x, 0.f); v0.y = fmaxf(v0.y * sc.y + sh.y, 0.f);
            v0.z = fmaxf(v0.z * sc.z + sh.z, 0.f); v0.w = fmaxf(v0.w * sc.w + sh.w, 0.f);
            v1.x = fmaxf(v1.x * sc.x + sh.x, 0.f); v1.y = fmaxf(v1.y * sc.y + sh.y, 0.f);
            v1.z = fmaxf(v1.z * sc.z + sh.z, 0.f); v1.w = fmaxf(v1.w * sc.w + sh.w, 0.f);
            v2.x = fmaxf(v2.x * sc.x + sh.x, 0.f); v2.y = fmaxf(v2.y * sc.y + sh.y, 0.f);
            v2.z = fmaxf(v2.z * sc.z + sh.z, 0.f); v2.w = fmaxf(v2.w * sc.w + sh.w, 0.f);
            v3.x = fmaxf(v3.x * sc.x + sh.x, 0.f); v3.y = fmaxf(v3.y * sc.y + sh.y, 0.f);
            v3.z = fmaxf(v3.z * sc.z + sh.z, 0.f); v3.w = fmaxf(v3.w * sc.w + sh.w, 0.f);
        }
        acc.x += v0.x + v1.x + v2.x + v3.x;
        acc.y += v0.y + v1.y + v2.y + v3.y;
        acc.z += v0.z + v1.z + v2.z + v3.z;
        acc.w += v0.w + v1.w + v2.w + v3.w;
    }
    for (; j < e; j++) {
        int nb = g_col[j];
        float4 v = *(const float4*)(feat + (size_t)nb * DD + c);
        if (LAYER == 1) {
            v.x = fmaxf(v.x * sc.x + sh.x, 0.f); v.y = fmaxf(v.y * sc.y + sh.y, 0.f);
            v.z = fmaxf(v.z * sc.z + sh.z, 0.f); v.w = fmaxf(v.w * sc.w + sh.w, 0.f);
        }
        acc.x += v.x; acc.y += v.y; acc.z += v.z; acc.w += v.w;
    }

    float inv = 1.0f / (float)(e - s + 1);
    acc.x *= inv; acc.y *= inv; acc.z *= inv; acc.w *= inv;
    *(float4*)(g_agg + (size_t)node * DD + c) = acc;
}

// ---------------- TF32 helpers ----------------------------------------------
__device__ __forceinline__ uint32_t f2tf32(float x) {
    uint32_t r;
    asm("cvt.rna.tf32.f32 %0, %1;" : "=r"(r) : "f"(x));
    return r;
}

__device__ __forceinline__ void mma_tf32(float* c, const uint32_t* a,
                                         const uint32_t* b) {
    asm volatile(
        "mma.sync.aligned.m16n8k8.row.col.f32.tf32.tf32.f32 "
        "{%0,%1,%2,%3}, {%4,%5,%6,%7}, {%8,%9}, {%0,%1,%2,%3};\n"
        : "+f"(c[0]), "+f"(c[1]), "+f"(c[2]), "+f"(c[3])
        : "r"(a[0]), "r"(a[1]), "r"(a[2]), "r"(a[3]), "r"(b[0]), "r"(b[1]));
}

// ---------------- fused dual GEMM via TF32 mma.sync --------------------------
// hpre = A@Wa^T + agg@Wb^T + bias.  LAYER 1 applies BN+ReLU to A during staging.
template<int LAYER>
__global__ void __launch_bounds__(512, 1) gemm_dual_kernel(
    const float* __restrict__ xin,
    const float* __restrict__ Wa, const float* __restrict__ Wb,
    const float* __restrict__ ba, const float* __restrict__ bb) {
    extern __shared__ float sm[];
    float* sW    = sm;                   // 256 x SP (tf32 bits, [k][f])
    float* sIn   = sm + 256 * SP;        // 128 x SP (tf32 bits, [node][k])
    float* sBias = sIn + 128 * SP;       // 128
    const float* A = (LAYER == 0) ? xin : g_hpre;
    const float* B = g_agg;
    int tid = threadIdx.x;

    for (int i = tid; i < DD * DD; i += 512) {
        int f = i >> 7, k = i & 127;
        sW[k * SP + f]        = __uint_as_float(f2tf32(Wa[i]));
        sW[(k + DD) * SP + f] = __uint_as_float(f2tf32(Wb[i]));
    }
    if (tid < DD) sBias[tid] = ba[tid] + bb[tid];

    int warp = tid >> 5, lane = tid & 31;
    int warpM = warp & 3, warpN = warp >> 2;      // 4x4 warp grid
    int g = lane >> 2, t = lane & 3;
    int cb = warpN * 32;                          // warp's col base

    float csum[4][2], csq[4][2];                  // BN partials (persist)
    #pragma unroll
    for (int n = 0; n < 4; n++) {
        csum[n][0] = csum[n][1] = 0.f;
        csq[n][0]  = csq[n][1]  = 0.f;
    }

    const int NT = (NN + 127) / 128;
    for (int tile = blockIdx.x; tile < NT; tile += gridDim.x) {
        int base = tile * 128;
        float C[2][4][4];
        #pragma unroll
        for (int m = 0; m < 2; m++)
            #pragma unroll
            for (int n = 0; n < 4; n++)
                #pragma unroll
                for (int r = 0; r < 4; r++) C[m][n][r] = 0.f;

        #pragma unroll
        for (int half = 0; half < 2; half++) {
            const float* src = (half == 0) ? A : B;
            const float* ws  = sW + half * DD * SP;
            __syncthreads();   // prior consumers done (covers sW/sBias 1st use)
            for (int i = tid; i < 128 * 32; i += 512) {
                int n = i >> 5, q = i & 31;
                int node = base + n;
                float4 v = make_float4(0.f, 0.f, 0.f, 0.f);
                if (node < NN)
                    v = *(const float4*)(src + (size_t)node * DD + q * 4);
                if (LAYER == 1 && half == 0) {   // A = relu(bn(hpre))
                    float4 sc = *(const float4*)(g_scale + q * 4);
                    float4 sh = *(const float4*)(g_shift + q * 4);
                    v.x = fmaxf(v.x * sc.x + sh.x, 0.f);
                    v.y = fmaxf(v.y * sc.y + sh.y, 0.f);
                    v.z = fmaxf(v.z * sc.z + sh.z, 0.f);
                    v.w = fmaxf(v.w * sc.w + sh.w, 0.f);
                }
                float4 o;
                o.x = __uint_as_float(f2tf32(v.x));
                o.y = __uint_as_float(f2tf32(v.y));
                o.z = __uint_as_float(f2tf32(v.z));
                o.w = __uint_as_float(f2tf32(v.w));
                *(float4*)(sIn + n * SP + q * 4) = o;
            }
            __syncthreads();

            #pragma unroll
            for (int kk = 0; kk < 16; kk++) {
                int k = kk * 8;
                uint32_t a[2][4];
                #pragma unroll
                for (int m = 0; m < 2; m++) {
                    const float* ap =
                        sIn + (warpM * 32 + m * 16 + g) * SP + k + t;
                    a[m][0] = __float_as_uint(ap[0]);
                    a[m][1] = __float_as_uint(ap[8 * SP]);
                    a[m][2] = __float_as_uint(ap[4]);
                    a[m][3] = __float_as_uint(ap[8 * SP + 4]);
                }
                uint32_t b[4][2];
                #pragma unroll
                for (int n = 0; n < 4; n++) {
                    const float* bp = ws + (k + t) * SP + cb + n * 8 + g;
                    b[n][0] = __float_as_uint(bp[0]);
                    b[n][1] = __float_as_uint(bp[4 * SP]);
                }
                #pragma unroll
                for (int m = 0; m < 2; m++)
                    #pragma unroll
                    for (int n = 0; n < 4; n++)
                        mma_tf32(C[m][n], a[m], b[n]);
            }
        }

        // epilogue: bias add, store, BN partials (only valid rows)
        #pragma unroll
        for (int m = 0; m < 2; m++) {
            int r0 = base + warpM * 32 + m * 16 + g;
            int r1 = r0 + 8;
            #pragma unroll
            for (int n = 0; n < 4; n++) {
                int col = cb + n * 8 + 2 * t;
                float b0v = sBias[col], b1v = sBias[col + 1];
                float v0 = C[m][n][0] + b0v, v1 = C[m][n][1] + b1v;
                float v2 = C[m][n][2] + b0v, v3 = C[m][n][3] + b1v;
                if (r0 < NN) {
                    *(float2*)(g_hpre + (size_t)r0 * DD + col) =
                        make_float2(v0, v1);
                    csum[n][0] += v0; csq[n][0] += v0 * v0;
                    csum[n][1] += v1; csq[n][1] += v1 * v1;
                }
                if (r1 < NN) {
                    *(float2*)(g_hpre + (size_t)r1 * DD + col) =
                        make_float2(v2, v3);
                    csum[n][0] += v2; csq[n][0] += v2 * v2;
                    csum[n][1] += v3; csq[n][1] += v3 * v3;
                }
            }
        }
    }

    // shfl-reduce BN partials over g (lanes sharing a column), then atomics
    #pragma unroll
    for (int n = 0; n < 4; n++)
        #pragma unroll
        for (int c = 0; c < 2; c++) {
            float s = csum[n][c], q = csq[n][c];
            #pragma unroll
            for (int o = 4; o < 32; o <<= 1) {
                s += __shfl_xor_sync(0xffffffffu, s, o);
                q += __shfl_xor_sync(0xffffffffu, q, o);
            }
            if (g == 0) {
                int col = cb + n * 8 + 2 * t + c;
                atomicAdd(&g_colsum[col], s);
                atomicAdd(&g_colsq[col], q);
            }
        }
}

// ---------------- BN finalize: stats -> scale/shift, reset stats ------------
__global__ void bn_finalize_kernel(const float* __restrict__ gamma,
                                   const float* __restrict__ beta) {
    int c = threadIdx.x;
    float mean = g_colsum[c] * (1.0f / NN);
    float var  = g_colsq[c]  * (1.0f / NN) - mean * mean;
    float sc   = gamma[c] * rsqrtf(var + 1e-5f);
    g_scale[c] = sc;
    g_shift[c] = beta[c] - mean * sc;
    g_colsum[c] = 0.f;
    g_colsq[c]  = 0.f;
}

// ---------------- head via TF32 mma: out = relu(bn(hpre)) @ Wh^T + bh -------
// 256 thr = 8 warps (4M x 2N); 128-node tile per block; K=128.
__global__ void __launch_bounds__(256) head_kernel(
    const float* __restrict__ Wh, const float* __restrict__ bh,
    float* __restrict__ outp) {
    extern __shared__ float sm[];
    float* sW  = sm;              // 128 x SP2 (tf32 bits, [k][f])
    float* sIn = sm + DD * SP2;   // 128 x SP  (tf32 bits, [node][k])
    int tid = threadIdx.x;

    for (int i = tid; i < 64 * DD; i += 256) {
        int f = i >> 7, k = i & 127;
        sW[k * SP2 + f] = __uint_as_float(f2tf32(Wh[i]));
    }

    int base = blockIdx.x * 128;
    for (int i = tid; i < 128 * 32; i += 256) {
        int n = i >> 5, q = i & 31;
        int node = base + n;
        float4 v = make_float4(0.f, 0.f, 0.f, 0.f);
        if (node < NN) {
            v = *(const float4*)(g_hpre + (size_t)node * DD + q * 4);
            float4 sc = *(const float4*)(g_scale + q * 4);
            float4 sh = *(const float4*)(g_shift + q * 4);
            v.x = fmaxf(v.x * sc.x + sh.x, 0.f);
            v.y = fmaxf(v.y * sc.y + sh.y, 0.f);
            v.z = fmaxf(v.z * sc.z + sh.z, 0.f);
            v.w = fmaxf(v.w * sc.w + sh.w, 0.f);
        }
        float4 o;
        o.x = __uint_as_float(f2tf32(v.x));
        o.y = __uint_as_float(f2tf32(v.y));
        o.z = __uint_as_float(f2tf32(v.z));
        o.w = __uint_as_float(f2tf32(v.w));
        *(float4*)(sIn + n * SP + q * 4) = o;
    }
    __syncthreads();

    int warp = tid >> 5, lane = tid & 31;
    int warpM = warp & 3, warpN = warp >> 2;   // 4 x 2
    int g = lane >> 2, t = lane & 3;
    int cb = warpN * 32;

    float C[2][4][4];
    #pragma unroll
    for (int m = 0; m < 2; m++)
        #pragma unroll
        for (int n = 0; n < 4; n++)
            #pragma unroll
            for (int r = 0; r < 4; r++) C[m][n][r] = 0.f;

    #pragma unroll
    for (int kk = 0; kk < 16; kk++) {
        int k = kk * 8;
        uint32_t a[2][4];
        #pragma unroll
        for (int m = 0; m < 2; m++) {
            const float* ap = sIn + (warpM * 32 + m * 16 + g) * SP + k + t;
            a[m][0] = __float_as_uint(ap[0]);
            a[m][1] = __float_as_uint(ap[8 * SP]);
            a[m][2] = __float_as_uint(ap[4]);
            a[m][3] = __float_as_uint(ap[8 * SP + 4]);
        }
        uint32_t b[4][2];
        #pragma unroll
        for (int n = 0; n < 4; n++) {
            const float* bp = sW + (k + t) * SP2 + cb + n * 8 + g;
            b[n][0] = __float_as_uint(bp[0]);
            b[n][1] = __float_as_uint(bp[4 * SP2]);
        }
        #pragma unroll
        for (int m = 0; m < 2; m++)
            #pragma unroll
            for (int n = 0; n < 4; n++)
                mma_tf32(C[m][n], a[m], b[n]);
    }

    #pragma unroll
    for (int m = 0; m < 2; m++) {
        int r0 = base + warpM * 32 + m * 16 + g;
        int r1 = r0 + 8;
        #pragma unroll
        for (int n = 0; n < 4; n++) {
            int col = cb + n * 8 + 2 * t;
            float b0v = bh[col], b1v = bh[col + 1];
            if (r0 < NN)
                *(float2*)(outp + (size_t)r0 * 64 + col) =
                    make_float2(C[m][n][0] + b0v, C[m][n][1] + b1v);
            if (r1 < NN)
                *(float2*)(outp + (size_t)r1 * 64 + col) =
                    make_float2(C[m][n][2] + b0v, C[m][n][3] + b1v);
        }
    }
}

// ---------------- launch ----------------------------------------------------
extern "C" void kernel_launch(void* const* d_in, const int* in_sizes, int n_in,
                              void* d_out, int out_size) {
    const float* x   = (const float*)d_in[0];
    const int*   ei  = (const int*)d_in[1];     // int32 (JAX default int)
    const float* Ws1 = (const float*)d_in[2];
    const float* bs1 = (const float*)d_in[3];
    const float* Wn1 = (const float*)d_in[4];
    const float* bn1 = (const float*)d_in[5];
    const float* g1  = (const float*)d_in[6];
    const float* be1 = (const float*)d_in[7];
    const float* Ws2 = (const float*)d_in[8];
    const float* bs2 = (const float*)d_in[9];
    const float* Wn2 = (const float*)d_in[10];
    const float* bn2 = (const float*)d_in[11];
    const float* g2  = (const float*)d_in[12];
    const float* be2 = (const float*)d_in[13];
    const float* Wh  = (const float*)d_in[14];
    const float* bh  = (const float*)d_in[15];
    float* out = (float*)d_out;

    const int GEMM_SMEM = (256 * SP + 128 * SP + 128) * 4;   // 203264 B
    const int HEAD_SMEM = (DD * SP2 + 128 * SP) * 4;         // 102400 B
    cudaFuncSetAttribute(gemm_dual_kernel<0>,
                         cudaFuncAttributeMaxDynamicSharedMemorySize, GEMM_SMEM);
    cudaFuncSetAttribute(gemm_dual_kernel<1>,
                         cudaFuncAttributeMaxDynamicSharedMemorySize, GEMM_SMEM);
    cudaFuncSetAttribute(head_kernel,
                         cudaFuncAttributeMaxDynamicSharedMemorySize, HEAD_SMEM);

    // CSR build (once; reused by both layers)
    zero_kernel<<<(NN + 255) / 256, 256>>>();
    count_kernel<<<(EE + 255) / 256, 256>>>(ei);
    scan_kernel<<<1, 1024>>>();
    scatter_kernel<<<(EE + 255) / 256, 256>>>(ei);

    // layer 1
    aggregate_kernel<0><<<(NN * 32 + 255) / 256, 256>>>(x);
    gemm_dual_kernel<0><<<148, 512, GEMM_SMEM>>>(x, Ws1, Wn1, bs1, bn1);
    bn_finalize_kernel<<<1, 128>>>(g1, be1);

    // layer 2 (BN+ReLU of layer 1 applied on the fly)
    aggregate_kernel<1><<<(NN * 32 + 255) / 256, 256>>>(x);
    gemm_dual_kernel<1><<<148, 512, GEMM_SMEM>>>(x, Ws2, Wn2, bs2, bn2);
    bn_finalize_kernel<<<1, 128>>>(g2, be2);

    // head (BN+ReLU of layer 2 applied on the fly)
    head_kernel<<<(NN + 127) / 128, 256, HEAD_SMEM>>>(Wh, bh, out);
}

// round 11
// speedup vs baseline: 4.5857x; 1.0504x over previous
#include <cuda_runtime.h>
#include <cuda_fp16.h>
#include <cstdint>

#define NN 100000
#define DD 128
#define EE 1600000
#define SP 132     // padded smem row stride (floats) for mma staging
#define SP2 68     // padded stride for head weight rows (64 cols)

// ---------------- scratch (device globals; no allocations allowed) ----------
__device__ __align__(16) float  g_agg [(size_t)NN * DD]; // normalized aggregation
__device__ __align__(16) float  g_hpre[(size_t)NN * DD]; // pre-BN activations
__device__ __align__(16) __half g_f16 [(size_t)NN * DD]; // fp16 gather buffer
__device__ int   g_deg   [NN];
__device__ int   g_cursor[NN];
__device__ int   g_rowptr[NN + 1];
__device__ int   g_col   [2 * EE];
__device__ float g_colsum[DD];
__device__ float g_colsq [DD];
__device__ __align__(16) float g_scale[DD];
__device__ __align__(16) float g_shift[DD];

// ---------------- CSR build --------------------------------------------------
__global__ void zero_kernel() {
    int i = blockIdx.x * blockDim.x + threadIdx.x;
    if (i < NN) { g_deg[i] = 0; g_cursor[i] = 0; }
    if (i < DD) { g_colsum[i] = 0.f; g_colsq[i] = 0.f; }
}

__global__ void count_kernel(const int* __restrict__ ei) {
    int e = blockIdx.x * blockDim.x + threadIdx.x;
    if (e >= EE) return;
    int a = ei[e], b = ei[EE + e];
    atomicAdd(&g_deg[a], 1);
    atomicAdd(&g_deg[b], 1);
}

// single-block scan over g_deg -> g_rowptr
__global__ void scan_kernel() {
    __shared__ int warp_sums[32];
    int tid = threadIdx.x;            // 1024 threads
    int lane = tid & 31, wid = tid >> 5;
    int running = 0;
    for (int base = 0; base < NN; base += 1024) {
        int i = base + tid;
        int v = (i < NN) ? g_deg[i] : 0;
        int x = v;
        #pragma unroll
        for (int o = 1; o < 32; o <<= 1) {
            int y = __shfl_up_sync(0xffffffffu, x, o);
            if (lane >= o) x += y;
        }
        if (lane == 31) warp_sums[wid] = x;
        __syncthreads();
        if (wid == 0) {
            int s = warp_sums[lane];
            #pragma unroll
            for (int o = 1; o < 32; o <<= 1) {
                int y = __shfl_up_sync(0xffffffffu, s, o);
                if (lane >= o) s += y;
            }
            warp_sums[lane] = s;
        }
        __syncthreads();
        int incl = running + (wid > 0 ? warp_sums[wid - 1] : 0) + x;
        if (i < NN) g_rowptr[i + 1] = incl;
        running += warp_sums[31];
        __syncthreads();
    }
    if (tid == 0) g_rowptr[0] = 0;
}

__global__ void scatter_kernel(const int* __restrict__ ei) {
    int e = blockIdx.x * blockDim.x + threadIdx.x;
    if (e >= EE) return;
    int a = ei[e], b = ei[EE + e];
    int pb = g_rowptr[b] + atomicAdd(&g_cursor[b], 1);
    g_col[pb] = a;
    int pa = g_rowptr[a] + atomicAdd(&g_cursor[a], 1);
    g_col[pa] = b;
}

// ---------------- fp16 conversion passes -------------------------------------
// MODE 0: g_f16 = fp16(x).  MODE 1: g_f16 = fp16(relu(bn(g_hpre))).
template<int MODE>
__global__ void tohalf_kernel(const float* __restrict__ xin) {
    int idx = blockIdx.x * blockDim.x + threadIdx.x;
    if (idx >= NN * 32) return;
    float4 v;
    if (MODE == 0) {
        v = ((const float4*)xin)[idx];
    } else {
        v = ((const float4*)g_hpre)[idx];
        int q = idx & 31;
        float4 sc = *(const float4*)(g_scale + q * 4);
        float4 sh = *(const float4*)(g_shift + q * 4);
        v.x = fmaxf(v.x * sc.x + sh.x, 0.f);
        v.y = fmaxf(v.y * sc.y + sh.y, 0.f);
        v.z = fmaxf(v.z * sc.z + sh.z, 0.f);
        v.w = fmaxf(v.w * sc.w + sh.w, 0.f);
    }
    __half2 h0 = __float22half2_rn(make_float2(v.x, v.y));
    __half2 h1 = __float22half2_rn(make_float2(v.z, v.w));
    uint2 o;
    o.x = *(uint32_t*)&h0;
    o.y = *(uint32_t*)&h1;
    ((uint2*)g_f16)[idx] = o;
}

// ---------------- gather-side mean aggregation: warp per node, fp16 source ---
__device__ __forceinline__ float4 h4f(uint2 r) {
    __half2 a = *(__half2*)&r.x;
    __half2 b = *(__half2*)&r.y;
    float2 fa = __half22float2(a), fb = __half22float2(b);
    return make_float4(fa.x, fa.y, fb.x, fb.y);
}

__global__ void __launch_bounds__(256) aggregate_kernel() {
    int node = (int)((blockIdx.x * blockDim.x + threadIdx.x) >> 5);
    if (node >= NN) return;
    int lane = threadIdx.x & 31;
    int c = lane * 4;
    const __half* feat = g_f16;

    float4 acc = h4f(*(const uint2*)(feat + (size_t)node * DD + c)); // self loop
    int s = g_rowptr[node];
    int e = g_rowptr[node + 1];

    int j = s;
    for (; j + 4 <= e; j += 4) {
        int n0 = g_col[j + 0], n1 = g_col[j + 1];
        int n2 = g_col[j + 2], n3 = g_col[j + 3];
        float4 v0 = h4f(*(const uint2*)(feat + (size_t)n0 * DD + c));
        float4 v1 = h4f(*(const uint2*)(feat + (size_t)n1 * DD + c));
        float4 v2 = h4f(*(const uint2*)(feat + (size_t)n2 * DD + c));
        float4 v3 = h4f(*(const uint2*)(feat + (size_t)n3 * DD + c));
        acc.x += v0.x + v1.x + v2.x + v3.x;
        acc.y += v0.y + v1.y + v2.y + v3.y;
        acc.z += v0.z + v1.z + v2.z + v3.z;
        acc.w += v0.w + v1.w + v2.w + v3.w;
    }
    for (; j < e; j++) {
        int nb = g_col[j];
        float4 v = h4f(*(const uint2*)(feat + (size_t)nb * DD + c));
        acc.x += v.x; acc.y += v.y; acc.z += v.z; acc.w += v.w;
    }

    float inv = 1.0f / (float)(e - s + 1);
    acc.x *= inv; acc.y *= inv; acc.z *= inv; acc.w *= inv;
    *(float4*)(g_agg + (size_t)node * DD + c) = acc;
}

// ---------------- TF32 helpers ----------------------------------------------
__device__ __forceinline__ uint32_t f2tf32(float x) {
    uint32_t r;
    asm("cvt.rna.tf32.f32 %0, %1;" : "=r"(r) : "f"(x));
    return r;
}

__device__ __forceinline__ void mma_tf32(float* c, const uint32_t* a,
                                         const uint32_t* b) {
    asm volatile(
        "mma.sync.aligned.m16n8k8.row.col.f32.tf32.tf32.f32 "
        "{%0,%1,%2,%3}, {%4,%5,%6,%7}, {%8,%9}, {%0,%1,%2,%3};\n"
        : "+f"(c[0]), "+f"(c[1]), "+f"(c[2]), "+f"(c[3])
        : "r"(a[0]), "r"(a[1]), "r"(a[2]), "r"(a[3]), "r"(b[0]), "r"(b[1]));
}

// ---------------- fused dual GEMM via TF32 mma.sync --------------------------
// hpre = A@Wa^T + agg@Wb^T + bias.  LAYER 1 applies BN+ReLU to A during staging.
template<int LAYER>
__global__ void __launch_bounds__(512, 1) gemm_dual_kernel(
    const float* __restrict__ xin,
    const float* __restrict__ Wa, const float* __restrict__ Wb,
    const float* __restrict__ ba, const float* __restrict__ bb) {
    extern __shared__ float sm[];
    float* sW    = sm;                   // 256 x SP (tf32 bits, [k][f])
    float* sIn   = sm + 256 * SP;        // 128 x SP (tf32 bits, [node][k])
    float* sBias = sIn + 128 * SP;       // 128
    const float* A = (LAYER == 0) ? xin : g_hpre;
    const float* B = g_agg;
    int tid = threadIdx.x;

    for (int i = tid; i < DD * DD; i += 512) {
        int f = i >> 7, k = i & 127;
        sW[k * SP + f]        = __uint_as_float(f2tf32(Wa[i]));
        sW[(k + DD) * SP + f] = __uint_as_float(f2tf32(Wb[i]));
    }
    if (tid < DD) sBias[tid] = ba[tid] + bb[tid];

    int warp = tid >> 5, lane = tid & 31;
    int warpM = warp & 3, warpN = warp >> 2;      // 4x4 warp grid
    int g = lane >> 2, t = lane & 3;
    int cb = warpN * 32;                          // warp's col base

    float csum[4][2], csq[4][2];                  // BN partials (persist)
    #pragma unroll
    for (int n = 0; n < 4; n++) {
        csum[n][0] = csum[n][1] = 0.f;
        csq[n][0]  = csq[n][1]  = 0.f;
    }

    const int NT = (NN + 127) / 128;
    for (int tile = blockIdx.x; tile < NT; tile += gridDim.x) {
        int base = tile * 128;
        float C[2][4][4];
        #pragma unroll
        for (int m = 0; m < 2; m++)
            #pragma unroll
            for (int n = 0; n < 4; n++)
                #pragma unroll
                for (int r = 0; r < 4; r++) C[m][n][r] = 0.f;

        #pragma unroll
        for (int half = 0; half < 2; half++) {
            const float* src = (half == 0) ? A : B;
            const float* ws  = sW + half * DD * SP;
            __syncthreads();   // prior consumers done (covers sW/sBias 1st use)
            for (int i = tid; i < 128 * 32; i += 512) {
                int n = i >> 5, q = i & 31;
                int node = base + n;
                float4 v = make_float4(0.f, 0.f, 0.f, 0.f);
                if (node < NN)
                    v = *(const float4*)(src + (size_t)node * DD + q * 4);
                if (LAYER == 1 && half == 0) {   // A = relu(bn(hpre))
                    float4 sc = *(const float4*)(g_scale + q * 4);
                    float4 sh = *(const float4*)(g_shift + q * 4);
                    v.x = fmaxf(v.x * sc.x + sh.x, 0.f);
                    v.y = fmaxf(v.y * sc.y + sh.y, 0.f);
                    v.z = fmaxf(v.z * sc.z + sh.z, 0.f);
                    v.w = fmaxf(v.w * sc.w + sh.w, 0.f);
                }
                float4 o;
                o.x = __uint_as_float(f2tf32(v.x));
                o.y = __uint_as_float(f2tf32(v.y));
                o.z = __uint_as_float(f2tf32(v.z));
                o.w = __uint_as_float(f2tf32(v.w));
                *(float4*)(sIn + n * SP + q * 4) = o;
            }
            __syncthreads();

            #pragma unroll
            for (int kk = 0; kk < 16; kk++) {
                int k = kk * 8;
                uint32_t a[2][4];
                #pragma unroll
                for (int m = 0; m < 2; m++) {
                    const float* ap =
                        sIn + (warpM * 32 + m * 16 + g) * SP + k + t;
                    a[m][0] = __float_as_uint(ap[0]);
                    a[m][1] = __float_as_uint(ap[8 * SP]);
                    a[m][2] = __float_as_uint(ap[4]);
                    a[m][3] = __float_as_uint(ap[8 * SP + 4]);
                }
                uint32_t b[4][2];
                #pragma unroll
                for (int n = 0; n < 4; n++) {
                    const float* bp = ws + (k + t) * SP + cb + n * 8 + g;
                    b[n][0] = __float_as_uint(bp[0]);
                    b[n][1] = __float_as_uint(bp[4 * SP]);
                }
                #pragma unroll
                for (int m = 0; m < 2; m++)
                    #pragma unroll
                    for (int n = 0; n < 4; n++)
                        mma_tf32(C[m][n], a[m], b[n]);
            }
        }

        // epilogue: bias add, store, BN partials (only valid rows)
        #pragma unroll
        for (int m = 0; m < 2; m++) {
            int r0 = base + warpM * 32 + m * 16 + g;
            int r1 = r0 + 8;
            #pragma unroll
            for (int n = 0; n < 4; n++) {
                int col = cb + n * 8 + 2 * t;
                float b0v = sBias[col], b1v = sBias[col + 1];
                float v0 = C[m][n][0] + b0v, v1 = C[m][n][1] + b1v;
                float v2 = C[m][n][2] + b0v, v3 = C[m][n][3] + b1v;
                if (r0 < NN) {
                    *(float2*)(g_hpre + (size_t)r0 * DD + col) =
                        make_float2(v0, v1);
                    csum[n][0] += v0; csq[n][0] += v0 * v0;
                    csum[n][1] += v1; csq[n][1] += v1 * v1;
                }
                if (r1 < NN) {
                    *(float2*)(g_hpre + (size_t)r1 * DD + col) =
                        make_float2(v2, v3);
                    csum[n][0] += v2; csq[n][0] += v2 * v2;
                    csum[n][1] += v3; csq[n][1] += v3 * v3;
                }
            }
        }
    }

    // shfl-reduce BN partials over g (lanes sharing a column), then atomics
    #pragma unroll
    for (int n = 0; n < 4; n++)
        #pragma unroll
        for (int c = 0; c < 2; c++) {
            float s = csum[n][c], q = csq[n][c];
            #pragma unroll
            for (int o = 4; o < 32; o <<= 1) {
                s += __shfl_xor_sync(0xffffffffu, s, o);
                q += __shfl_xor_sync(0xffffffffu, q, o);
            }
            if (g == 0) {
                int col = cb + n * 8 + 2 * t + c;
                atomicAdd(&g_colsum[col], s);
                atomicAdd(&g_colsq[col], q);
            }
        }
}

// ---------------- BN finalize: stats -> scale/shift, reset stats ------------
__global__ void bn_finalize_kernel(const float* __restrict__ gamma,
                                   const float* __restrict__ beta) {
    int c = threadIdx.x;
    float mean = g_colsum[c] * (1.0f / NN);
    float var  = g_colsq[c]  * (1.0f / NN) - mean * mean;
    float sc   = gamma[c] * rsqrtf(var + 1e-5f);
    g_scale[c] = sc;
    g_shift[c] = beta[c] - mean * sc;
    g_colsum[c] = 0.f;
    g_colsq[c]  = 0.f;
}

// ---------------- head via TF32 mma: out = relu(bn(hpre)) @ Wh^T + bh -------
// 256 thr = 8 warps (4M x 2N); 128-node tile per block; K=128.
__global__ void __launch_bounds__(256) head_kernel(
    const float* __restrict__ Wh, const float* __restrict__ bh,
    float* __restrict__ outp) {
    extern __shared__ float sm[];
    float* sW  = sm;              // 128 x SP2 (tf32 bits, [k][f])
    float* sIn = sm + DD * SP2;   // 128 x SP  (tf32 bits, [node][k])
    int tid = threadIdx.x;

    for (int i = tid; i < 64 * DD; i += 256) {
        int f = i >> 7, k = i & 127;
        sW[k * SP2 + f] = __uint_as_float(f2tf32(Wh[i]));
    }

    int base = blockIdx.x * 128;
    for (int i = tid; i < 128 * 32; i += 256) {
        int n = i >> 5, q = i & 31;
        int node = base + n;
        float4 v = make_float4(0.f, 0.f, 0.f, 0.f);
        if (node < NN) {
            v = *(const float4*)(g_hpre + (size_t)node * DD + q * 4);
            float4 sc = *(const float4*)(g_scale + q * 4);
            float4 sh = *(const float4*)(g_shift + q * 4);
            v.x = fmaxf(v.x * sc.x + sh.x, 0.f);
            v.y = fmaxf(v.y * sc.y + sh.y, 0.f);
            v.z = fmaxf(v.z * sc.z + sh.z, 0.f);
            v.w = fmaxf(v.w * sc.w + sh.w, 0.f);
        }
        float4 o;
        o.x = __uint_as_float(f2tf32(v.x));
        o.y = __uint_as_float(f2tf32(v.y));
        o.z = __uint_as_float(f2tf32(v.z));
        o.w = __uint_as_float(f2tf32(v.w));
        *(float4*)(sIn + n * SP + q * 4) = o;
    }
    __syncthreads();

    int warp = tid >> 5, lane = tid & 31;
    int warpM = warp & 3, warpN = warp >> 2;   // 4 x 2
    int g = lane >> 2, t = lane & 3;
    int cb = warpN * 32;

    float C[2][4][4];
    #pragma unroll
    for (int m = 0; m < 2; m++)
        #pragma unroll
        for (int n = 0; n < 4; n++)
            #pragma unroll
            for (int r = 0; r < 4; r++) C[m][n][r] = 0.f;

    #pragma unroll
    for (int kk = 0; kk < 16; kk++) {
        int k = kk * 8;
        uint32_t a[2][4];
        #pragma unroll
        for (int m = 0; m < 2; m++) {
            const float* ap = sIn + (warpM * 32 + m * 16 + g) * SP + k + t;
            a[m][0] = __float_as_uint(ap[0]);
            a[m][1] = __float_as_uint(ap[8 * SP]);
            a[m][2] = __float_as_uint(ap[4]);
            a[m][3] = __float_as_uint(ap[8 * SP + 4]);
        }
        uint32_t b[4][2];
        #pragma unroll
        for (int n = 0; n < 4; n++) {
            const float* bp = sW + (k + t) * SP2 + cb + n * 8 + g;
            b[n][0] = __float_as_uint(bp[0]);
            b[n][1] = __float_as_uint(bp[4 * SP2]);
        }
        #pragma unroll
        for (int m = 0; m < 2; m++)
            #pragma unroll
            for (int n = 0; n < 4; n++)
                mma_tf32(C[m][n], a[m], b[n]);
    }

    #pragma unroll
    for (int m = 0; m < 2; m++) {
        int r0 = base + warpM * 32 + m * 16 + g;
        int r1 = r0 + 8;
        #pragma unroll
        for (int n = 0; n < 4; n++) {
            int col = cb + n * 8 + 2 * t;
            float b0v = bh[col], b1v = bh[col + 1];
            if (r0 < NN)
                *(float2*)(outp + (size_t)r0 * 64 + col) =
                    make_float2(C[m][n][0] + b0v, C[m][n][1] + b1v);
            if (r1 < NN)
                *(float2*)(outp + (size_t)r1 * 64 + col) =
                    make_float2(C[m][n][2] + b0v, C[m][n][3] + b1v);
        }
    }
}

// ---------------- launch ----------------------------------------------------
extern "C" void kernel_launch(void* const* d_in, const int* in_sizes, int n_in,
                              void* d_out, int out_size) {
    const float* x   = (const float*)d_in[0];
    const int*   ei  = (const int*)d_in[1];     // int32 (JAX default int)
    const float* Ws1 = (const float*)d_in[2];
    const float* bs1 = (const float*)d_in[3];
    const float* Wn1 = (const float*)d_in[4];
    const float* bn1 = (const float*)d_in[5];
    const float* g1  = (const float*)d_in[6];
    const float* be1 = (const float*)d_in[7];
    const float* Ws2 = (const float*)d_in[8];
    const float* bs2 = (const float*)d_in[9];
    const float* Wn2 = (const float*)d_in[10];
    const float* bn2 = (const float*)d_in[11];
    const float* g2  = (const float*)d_in[12];
    const float* be2 = (const float*)d_in[13];
    const float* Wh  = (const float*)d_in[14];
    const float* bh  = (const float*)d_in[15];
    float* out = (float*)d_out;

    const int GEMM_SMEM = (256 * SP + 128 * SP + 128) * 4;   // 203264 B
    const int HEAD_SMEM = (DD * SP2 + 128 * SP) * 4;         // 102400 B
    cudaFuncSetAttribute(gemm_dual_kernel<0>,
                         cudaFuncAttributeMaxDynamicSharedMemorySize, GEMM_SMEM);
    cudaFuncSetAttribute(gemm_dual_kernel<1>,
                         cudaFuncAttributeMaxDynamicSharedMemorySize, GEMM_SMEM);
    cudaFuncSetAttribute(head_kernel,
                         cudaFuncAttributeMaxDynamicSharedMemorySize, HEAD_SMEM);

    const int NT32 = (NN * 32 + 255) / 256;

    // CSR build (once; reused by both layers)
    zero_kernel<<<(NN + 255) / 256, 256>>>();
    count_kernel<<<(EE + 255) / 256, 256>>>(ei);
    scan_kernel<<<1, 1024>>>();
    scatter_kernel<<<(EE + 255) / 256, 256>>>(ei);

    // layer 1: fp16(x) -> gather -> dual gemm -> bn stats
    tohalf_kernel<0><<<NT32, 256>>>(x);
    aggregate_kernel<<<NT32, 256>>>();
    gemm_dual_kernel<0><<<148, 512, GEMM_SMEM>>>(x, Ws1, Wn1, bs1, bn1);
    bn_finalize_kernel<<<1, 128>>>(g1, be1);

    // layer 2: fp16(relu(bn(hpre))) -> gather -> dual gemm -> bn stats
    tohalf_kernel<1><<<NT32, 256>>>(x);
    aggregate_kernel<<<NT32, 256>>>();
    gemm_dual_kernel<1><<<148, 512, GEMM_SMEM>>>(x, Ws2, Wn2, bs2, bn2);
    bn_finalize_kernel<<<1, 128>>>(g2, be2);

    // head (BN+ReLU of layer 2 applied on the fly)
    head_kernel<<<(NN + 127) / 128, 256, HEAD_SMEM>>>(Wh, bh, out);
}

// round 14
// speedup vs baseline: 5.7091x; 1.2450x over previous
#include <cuda_runtime.h>
#include <cuda_fp16.h>
#include <cstdint>

#define NN 100000
#define DD 128
#define EE 1600000
#define SPH 136    // smem row stride in halves for fp16 mma staging (128+8)
#define SP 132     // padded smem row stride (floats) for head tf32 staging
#define SP2 68     // padded stride for head weight rows (64 cols)

// ---------------- scratch (device globals; no allocations allowed) ----------
__device__ __align__(16) __half g_agg [(size_t)NN * DD]; // fp16 aggregation
__device__ __align__(16) float  g_hpre[(size_t)NN * DD]; // pre-BN activations
__device__ __align__(16) __half g_f16 [(size_t)NN * DD]; // fp16 feature buffer
__device__ int   g_deg   [NN];
__device__ int   g_cursor[NN];
__device__ int   g_rowptr[NN + 1];
__device__ int   g_col   [2 * EE];
__device__ float g_colsum[DD];
__device__ float g_colsq [DD];
__device__ __align__(16) float g_scale[DD];
__device__ __align__(16) float g_shift[DD];

// ---------------- CSR build --------------------------------------------------
__global__ void zero_kernel() {
    int i = blockIdx.x * blockDim.x + threadIdx.x;
    if (i < NN) { g_deg[i] = 0; g_cursor[i] = 0; }
    if (i < DD) { g_colsum[i] = 0.f; g_colsq[i] = 0.f; }
}

__global__ void count_kernel(const int* __restrict__ ei) {
    int e = blockIdx.x * blockDim.x + threadIdx.x;
    if (e >= EE) return;
    int a = ei[e], b = ei[EE + e];
    atomicAdd(&g_deg[a], 1);
    atomicAdd(&g_deg[b], 1);
}

// single-block scan over g_deg -> g_rowptr
__global__ void scan_kernel() {
    __shared__ int warp_sums[32];
    int tid = threadIdx.x;            // 1024 threads
    int lane = tid & 31, wid = tid >> 5;
    int running = 0;
    for (int base = 0; base < NN; base += 1024) {
        int i = base + tid;
        int v = (i < NN) ? g_deg[i] : 0;
        int x = v;
        #pragma unroll
        for (int o = 1; o < 32; o <<= 1) {
            int y = __shfl_up_sync(0xffffffffu, x, o);
            if (lane >= o) x += y;
        }
        if (lane == 31) warp_sums[wid] = x;
        __syncthreads();
        if (wid == 0) {
            int s = warp_sums[lane];
            #pragma unroll
            for (int o = 1; o < 32; o <<= 1) {
                int y = __shfl_up_sync(0xffffffffu, s, o);
                if (lane >= o) s += y;
            }
            warp_sums[lane] = s;
        }
        __syncthreads();
        int incl = running + (wid > 0 ? warp_sums[wid - 1] : 0) + x;
        if (i < NN) g_rowptr[i + 1] = incl;
        running += warp_sums[31];
        __syncthreads();
    }
    if (tid == 0) g_rowptr[0] = 0;
}

__global__ void scatter_kernel(const int* __restrict__ ei) {
    int e = blockIdx.x * blockDim.x + threadIdx.x;
    if (e >= EE) return;
    int a = ei[e], b = ei[EE + e];
    int pb = g_rowptr[b] + atomicAdd(&g_cursor[b], 1);
    g_col[pb] = a;
    int pa = g_rowptr[a] + atomicAdd(&g_cursor[a], 1);
    g_col[pa] = b;
}

// ---------------- fp16 conversion passes -------------------------------------
// MODE 0: g_f16 = fp16(x).  MODE 1: g_f16 = fp16(relu(bn(g_hpre))).
template<int MODE>
__global__ void tohalf_kernel(const float* __restrict__ xin) {
    int idx = blockIdx.x * blockDim.x + threadIdx.x;
    if (idx >= NN * 32) return;
    float4 v;
    if (MODE == 0) {
        v = ((const float4*)xin)[idx];
    } else {
        v = ((const float4*)g_hpre)[idx];
        int q = idx & 31;
        float4 sc = *(const float4*)(g_scale + q * 4);
        float4 sh = *(const float4*)(g_shift + q * 4);
        v.x = fmaxf(v.x * sc.x + sh.x, 0.f);
        v.y = fmaxf(v.y * sc.y + sh.y, 0.f);
        v.z = fmaxf(v.z * sc.z + sh.z, 0.f);
        v.w = fmaxf(v.w * sc.w + sh.w, 0.f);
    }
    __half2 h0 = __float22half2_rn(make_float2(v.x, v.y));
    __half2 h1 = __float22half2_rn(make_float2(v.z, v.w));
    uint2 o;
    o.x = *(uint32_t*)&h0;
    o.y = *(uint32_t*)&h1;
    ((uint2*)g_f16)[idx] = o;
}

// ---------------- aggregation: warp/node, 2 neighbors per LDG.128 ------------
// half 0 (lanes 0-15) fetches neighbor j, half 1 fetches j+1; lane covers 8
// consecutive cols (uint4 = 8 halves); shfl_xor(16) combines at the end.
__device__ __forceinline__ void acc8(float* acc, uint4 r) {
    __half2* h = (__half2*)&r;
    #pragma unroll
    for (int p = 0; p < 4; p++) {
        float2 f = __half22float2(h[p]);
        acc[p * 2 + 0] += f.x;
        acc[p * 2 + 1] += f.y;
    }
}

__global__ void __launch_bounds__(256) aggregate_kernel() {
    int node = (int)((blockIdx.x * blockDim.x + threadIdx.x) >> 5);
    if (node >= NN) return;
    int lane = threadIdx.x & 31;
    int half = lane >> 4, sub = lane & 15;
    const __half* base = g_f16 + (size_t)0;
    int coff = sub * 8;                       // column offset in halves

    float acc[8];
    #pragma unroll
    for (int r = 0; r < 8; r++) acc[r] = 0.f;

    if (half == 0)                            // self loop (half 0 only)
        acc8(acc, *(const uint4*)(base + (size_t)node * DD + coff));

    int s = g_rowptr[node];
    int e = g_rowptr[node + 1];
    int j = s;
    for (; j + 8 <= e; j += 8) {              // 4 pair-fetches in flight
        int n0 = g_col[j + 0 + half];
        int n1 = g_col[j + 2 + half];
        int n2 = g_col[j + 4 + half];
        int n3 = g_col[j + 6 + half];
        uint4 r0 = *(const uint4*)(base + (size_t)n0 * DD + coff);
        uint4 r1 = *(const uint4*)(base + (size_t)n1 * DD + coff);
        uint4 r2 = *(const uint4*)(base + (size_t)n2 * DD + coff);
        uint4 r3 = *(const uint4*)(base + (size_t)n3 * DD + coff);
        acc8(acc, r0); acc8(acc, r1); acc8(acc, r2); acc8(acc, r3);
    }
    for (; j + 2 <= e; j += 2) {
        int nb = g_col[j + half];
        acc8(acc, *(const uint4*)(base + (size_t)nb * DD + coff));
    }
    if (j < e && half == 0) {                 // odd remainder
        int nb = g_col[j];
        acc8(acc, *(const uint4*)(base + (size_t)nb * DD + coff));
    }

    #pragma unroll
    for (int r = 0; r < 8; r++)
        acc[r] += __shfl_xor_sync(0xffffffffu, acc[r], 16);

    if (half == 0) {
        float inv = 1.0f / (float)(e - s + 1);
        uint4 o;
        __half2* oh = (__half2*)&o;
        #pragma unroll
        for (int p = 0; p < 4; p++)
            oh[p] = __float22half2_rn(
                make_float2(acc[p * 2] * inv, acc[p * 2 + 1] * inv));
        *(uint4*)(g_agg + (size_t)node * DD + coff) = o;
    }
}

// ---------------- TF32 helpers (head only) -----------------------------------
__device__ __forceinline__ uint32_t f2tf32(float x) {
    uint32_t r;
    asm("cvt.rna.tf32.f32 %0, %1;" : "=r"(r) : "f"(x));
    return r;
}

__device__ __forceinline__ void mma_tf32(float* c, const uint32_t* a,
                                         const uint32_t* b) {
    asm volatile(
        "mma.sync.aligned.m16n8k8.row.col.f32.tf32.tf32.f32 "
        "{%0,%1,%2,%3}, {%4,%5,%6,%7}, {%8,%9}, {%0,%1,%2,%3};\n"
        : "+f"(c[0]), "+f"(c[1]), "+f"(c[2]), "+f"(c[3])
        : "r"(a[0]), "r"(a[1]), "r"(a[2]), "r"(a[3]), "r"(b[0]), "r"(b[1]));
}

// ---------------- fp16 mma helper --------------------------------------------
__device__ __forceinline__ void mma_f16(float* c, const uint32_t* a,
                                        const uint32_t* b) {
    asm volatile(
        "mma.sync.aligned.m16n8k16.row.col.f32.f16.f16.f32 "
        "{%0,%1,%2,%3}, {%4,%5,%6,%7}, {%8,%9}, {%0,%1,%2,%3};\n"
        : "+f"(c[0]), "+f"(c[1]), "+f"(c[2]), "+f"(c[3])
        : "r"(a[0]), "r"(a[1]), "r"(a[2]), "r"(a[3]), "r"(b[0]), "r"(b[1]));
}

// ---------------- fused dual GEMM via fp16 mma.sync --------------------------
// hpre = f16A@Wa^T + agg@Wb^T + bias.  A = g_f16 (fp16), B = g_agg (fp16).
// Weights stored [f][k] (no transpose), stride SPH halves (conflict-free).
__global__ void __launch_bounds__(512, 1) gemm_dual_kernel(
    const float* __restrict__ Wa, const float* __restrict__ Wb,
    const float* __restrict__ ba, const float* __restrict__ bb) {
    extern __shared__ __half smh[];
    __half* sWa  = smh;                  // 128 x SPH
    __half* sWb  = smh + 128 * SPH;      // 128 x SPH
    __half* sInA = smh + 256 * SPH;      // 128 x SPH
    __half* sInB = smh + 384 * SPH;      // 128 x SPH
    float*  sBias = (float*)(smh + 512 * SPH);   // 128 floats
    int tid = threadIdx.x;

    // stage weights as fp16, [f][k] layout (rows copied directly)
    for (int i = tid; i < 128 * 16; i += 512) {  // 8 floats per item
        int f = i >> 4, q = i & 15;
        const float4* wa = (const float4*)(Wa + f * DD + q * 8);
        const float4* wb = (const float4*)(Wb + f * DD + q * 8);
        float4 a0 = wa[0], a1 = wa[1];
        float4 b0 = wb[0], b1 = wb[1];
        uint4 oa, ob;
        __half2* ha = (__half2*)&oa;
        __half2* hb = (__half2*)&ob;
        ha[0] = __float22half2_rn(make_float2(a0.x, a0.y));
        ha[1] = __float22half2_rn(make_float2(a0.z, a0.w));
        ha[2] = __float22half2_rn(make_float2(a1.x, a1.y));
        ha[3] = __float22half2_rn(make_float2(a1.z, a1.w));
        hb[0] = __float22half2_rn(make_float2(b0.x, b0.y));
        hb[1] = __float22half2_rn(make_float2(b0.z, b0.w));
        hb[2] = __float22half2_rn(make_float2(b1.x, b1.y));
        hb[3] = __float22half2_rn(make_float2(b1.z, b1.w));
        *(uint4*)(sWa + f * SPH + q * 8) = oa;
        *(uint4*)(sWb + f * SPH + q * 8) = ob;
    }
    if (tid < DD) sBias[tid] = ba[tid] + bb[tid];

    int warp = tid >> 5, lane = tid & 31;
    int warpM = warp & 3, warpN = warp >> 2;      // 4x4 warp grid
    int g = lane >> 2, t = lane & 3;
    int cb = warpN * 32;                          // warp's col base

    float csum[4][2], csq[4][2];                  // BN partials (persist)
    #pragma unroll
    for (int n = 0; n < 4; n++) {
        csum[n][0] = csum[n][1] = 0.f;
        csq[n][0]  = csq[n][1]  = 0.f;
    }

    const int NT = (NN + 127) / 128;
    for (int tile = blockIdx.x; tile < NT; tile += gridDim.x) {
        int base = tile * 128;
        __syncthreads();   // prev tile consumed (covers weight/bias 1st use)

        // stage A (g_f16) and B (g_agg) rows: straight uint4 copies
        for (int i = tid; i < 128 * 16; i += 512) {
            int n = i >> 4, q = i & 15;
            int node = base + n;
            uint4 va = make_uint4(0, 0, 0, 0), vb = make_uint4(0, 0, 0, 0);
            if (node < NN) {
                va = *(const uint4*)(g_f16 + (size_t)node * DD + q * 8);
                vb = *(const uint4*)(g_agg + (size_t)node * DD + q * 8);
            }
            *(uint4*)(sInA + n * SPH + q * 8) = va;
            *(uint4*)(sInB + n * SPH + q * 8) = vb;
        }
        __syncthreads();

        float C[2][4][4];
        #pragma unroll
        for (int m = 0; m < 2; m++)
            #pragma unroll
            for (int n = 0; n < 4; n++)
                #pragma unroll
                for (int r = 0; r < 4; r++) C[m][n][r] = 0.f;

        #pragma unroll
        for (int ks = 0; ks < 16; ks++) {
            const __half* in = (ks < 8) ? sInA : sInB;
            const __half* ws = (ks < 8) ? sWa : sWb;
            int k = (ks & 7) * 16;
            uint32_t a[2][4];
            #pragma unroll
            for (int m = 0; m < 2; m++) {
                const __half* ap = in + (warpM * 32 + m * 16 + g) * SPH + k + 2 * t;
                a[m][0] = *(const uint32_t*)(ap);
                a[m][1] = *(const uint32_t*)(ap + 8 * SPH);
                a[m][2] = *(const uint32_t*)(ap + 8);
                a[m][3] = *(const uint32_t*)(ap + 8 * SPH + 8);
            }
            uint32_t b[4][2];
            #pragma unroll
            for (int n = 0; n < 4; n++) {
                const __half* bp = ws + (cb + n * 8 + g) * SPH + k + 2 * t;
                b[n][0] = *(const uint32_t*)(bp);
                b[n][1] = *(const uint32_t*)(bp + 8);
            }
            #pragma unroll
            for (int m = 0; m < 2; m++)
                #pragma unroll
                for (int n = 0; n < 4; n++)
                    mma_f16(C[m][n], a[m], b[n]);
        }

        // epilogue: bias add, store fp32 hpre, BN partials (only valid rows)
        #pragma unroll
        for (int m = 0; m < 2; m++) {
            int r0 = base + warpM * 32 + m * 16 + g;
            int r1 = r0 + 8;
            #pragma unroll
            for (int n = 0; n < 4; n++) {
                int col = cb + n * 8 + 2 * t;
                float b0v = sBias[col], b1v = sBias[col + 1];
                float v0 = C[m][n][0] + b0v, v1 = C[m][n][1] + b1v;
                float v2 = C[m][n][2] + b0v, v3 = C[m][n][3] + b1v;
                if (r0 < NN) {
                    *(float2*)(g_hpre + (size_t)r0 * DD + col) =
                        make_float2(v0, v1);
                    csum[n][0] += v0; csq[n][0] += v0 * v0;
                    csum[n][1] += v1; csq[n][1] += v1 * v1;
                }
                if (r1 < NN) {
                    *(float2*)(g_hpre + (size_t)r1 * DD + col) =
                        make_float2(v2, v3);
                    csum[n][0] += v2; csq[n][0] += v2 * v2;
                    csum[n][1] += v3; csq[n][1] += v3 * v3;
                }
            }
        }
    }

    // shfl-reduce BN partials over g (lanes sharing a column), then atomics
    #pragma unroll
    for (int n = 0; n < 4; n++)
        #pragma unroll
        for (int c = 0; c < 2; c++) {
            float s = csum[n][c], q = csq[n][c];
            #pragma unroll
            for (int o = 4; o < 32; o <<= 1) {
                s += __shfl_xor_sync(0xffffffffu, s, o);
                q += __shfl_xor_sync(0xffffffffu, q, o);
            }
            if (g == 0) {
                int col = cb + n * 8 + 2 * t + c;
                atomicAdd(&g_colsum[col], s);
                atomicAdd(&g_colsq[col], q);
            }
        }
}

// ---------------- BN finalize: stats -> scale/shift, reset stats ------------
__global__ void bn_finalize_kernel(const float* __restrict__ gamma,
                                   const float* __restrict__ beta) {
    int c = threadIdx.x;
    float mean = g_colsum[c] * (1.0f / NN);
    float var  = g_colsq[c]  * (1.0f / NN) - mean * mean;
    float sc   = gamma[c] * rsqrtf(var + 1e-5f);
    g_scale[c] = sc;
    g_shift[c] = beta[c] - mean * sc;
    g_colsum[c] = 0.f;
    g_colsq[c]  = 0.f;
}

// ---------------- head via TF32 mma: out = relu(bn(hpre)) @ Wh^T + bh -------
// 256 thr = 8 warps (4M x 2N); 128-node tile per block; K=128.
__global__ void __launch_bounds__(256) head_kernel(
    const float* __restrict__ Wh, const float* __restrict__ bh,
    float* __restrict__ outp) {
    extern __shared__ float sm[];
    float* sW  = sm;              // 128 x SP2 (tf32 bits, [k][f])
    float* sIn = sm + DD * SP2;   // 128 x SP  (tf32 bits, [node][k])
    int tid = threadIdx.x;

    for (int i = tid; i < 64 * DD; i += 256) {
        int f = i >> 7, k = i & 127;
        sW[k * SP2 + f] = __uint_as_float(f2tf32(Wh[i]));
    }

    int base = blockIdx.x * 128;
    for (int i = tid; i < 128 * 32; i += 256) {
        int n = i >> 5, q = i & 31;
        int node = base + n;
        float4 v = make_float4(0.f, 0.f, 0.f, 0.f);
        if (node < NN) {
            v = *(const float4*)(g_hpre + (size_t)node * DD + q * 4);
            float4 sc = *(const float4*)(g_scale + q * 4);
            float4 sh = *(const float4*)(g_shift + q * 4);
            v.x = fmaxf(v.x * sc.x + sh.x, 0.f);
            v.y = fmaxf(v.y * sc.y + sh.y, 0.f);
            v.z = fmaxf(v.z * sc.z + sh.z, 0.f);
            v.w = fmaxf(v.w * sc.w + sh.w, 0.f);
        }
        float4 o;
        o.x = __uint_as_float(f2tf32(v.x));
        o.y = __uint_as_float(f2tf32(v.y));
        o.z = __uint_as_float(f2tf32(v.z));
        o.w = __uint_as_float(f2tf32(v.w));
        *(float4*)(sIn + n * SP + q * 4) = o;
    }
    __syncthreads();

    int warp = tid >> 5, lane = tid & 31;
    int warpM = warp & 3, warpN = warp >> 2;   // 4 x 2
    int g = lane >> 2, t = lane & 3;
    int cb = warpN * 32;

    float C[2][4][4];
    #pragma unroll
    for (int m = 0; m < 2; m++)
        #pragma unroll
        for (int n = 0; n < 4; n++)
            #pragma unroll
            for (int r = 0; r < 4; r++) C[m][n][r] = 0.f;

    #pragma unroll
    for (int kk = 0; kk < 16; kk++) {
        int k = kk * 8;
        uint32_t a[2][4];
        #pragma unroll
        for (int m = 0; m < 2; m++) {
            const float* ap = sIn + (warpM * 32 + m * 16 + g) * SP + k + t;
            a[m][0] = __float_as_uint(ap[0]);
            a[m][1] = __float_as_uint(ap[8 * SP]);
            a[m][2] = __float_as_uint(ap[4]);
            a[m][3] = __float_as_uint(ap[8 * SP + 4]);
        }
        uint32_t b[4][2];
        #pragma unroll
        for (int n = 0; n < 4; n++) {
            const float* bp = sW + (k + t) * SP2 + cb + n * 8 + g;
            b[n][0] = __float_as_uint(bp[0]);
            b[n][1] = __float_as_uint(bp[4 * SP2]);
        }
        #pragma unroll
        for (int m = 0; m < 2; m++)
            #pragma unroll
            for (int n = 0; n < 4; n++)
                mma_tf32(C[m][n], a[m], b[n]);
    }

    #pragma unroll
    for (int m = 0; m < 2; m++) {
        int r0 = base + warpM * 32 + m * 16 + g;
        int r1 = r0 + 8;
        #pragma unroll
        for (int n = 0; n < 4; n++) {
            int col = cb + n * 8 + 2 * t;
            float b0v = bh[col], b1v = bh[col + 1];
            if (r0 < NN)
                *(float2*)(outp + (size_t)r0 * 64 + col) =
                    make_float2(C[m][n][0] + b0v, C[m][n][1] + b1v);
            if (r1 < NN)
                *(float2*)(outp + (size_t)r1 * 64 + col) =
                    make_float2(C[m][n][2] + b0v, C[m][n][3] + b1v);
        }
    }
}

// ---------------- launch ----------------------------------------------------
extern "C" void kernel_launch(void* const* d_in, const int* in_sizes, int n_in,
                              void* d_out, int out_size) {
    const float* x   = (const float*)d_in[0];
    const int*   ei  = (const int*)d_in[1];     // int32 (JAX default int)
    const float* Ws1 = (const float*)d_in[2];
    const float* bs1 = (const float*)d_in[3];
    const float* Wn1 = (const float*)d_in[4];
    const float* bn1 = (const float*)d_in[5];
    const float* g1  = (const float*)d_in[6];
    const float* be1 = (const float*)d_in[7];
    const float* Ws2 = (const float*)d_in[8];
    const float* bs2 = (const float*)d_in[9];
    const float* Wn2 = (const float*)d_in[10];
    const float* bn2 = (const float*)d_in[11];
    const float* g2  = (const float*)d_in[12];
    const float* be2 = (const float*)d_in[13];
    const float* Wh  = (const float*)d_in[14];
    const float* bh  = (const float*)d_in[15];
    float* out = (float*)d_out;

    const int GEMM_SMEM = 512 * SPH * 2 + 128 * 4;           // 139776+512 B
    const int HEAD_SMEM = (DD * SP2 + 128 * SP) * 4;         // 102400 B
    cudaFuncSetAttribute(gemm_dual_kernel,
                         cudaFuncAttributeMaxDynamicSharedMemorySize, GEMM_SMEM);
    cudaFuncSetAttribute(head_kernel,
                         cudaFuncAttributeMaxDynamicSharedMemorySize, HEAD_SMEM);

    const int NT32 = (NN * 32 + 255) / 256;

    // CSR build (once; reused by both layers)
    zero_kernel<<<(NN + 255) / 256, 256>>>();
    count_kernel<<<(EE + 255) / 256, 256>>>(ei);
    scan_kernel<<<1, 1024>>>();
    scatter_kernel<<<(EE + 255) / 256, 256>>>(ei);

    // layer 1: fp16(x) -> gather -> dual gemm -> bn stats
    tohalf_kernel<0><<<NT32, 256>>>(x);
    aggregate_kernel<<<NT32, 256>>>();
    gemm_dual_kernel<<<148, 512, GEMM_SMEM>>>(Ws1, Wn1, bs1, bn1);
    bn_finalize_kernel<<<1, 128>>>(g1, be1);

    // layer 2: fp16(relu(bn(hpre))) -> gather -> dual gemm -> bn stats
    tohalf_kernel<1><<<NT32, 256>>>(x);
    aggregate_kernel<<<NT32, 256>>>();
    gemm_dual_kernel<<<148, 512, GEMM_SMEM>>>(Ws2, Wn2, bs2, bn2);
    bn_finalize_kernel<<<1, 128>>>(g2, be2);

    // head (BN+ReLU of layer 2 applied on the fly)
    head_kernel<<<(NN + 127) / 128, 256, HEAD_SMEM>>>(Wh, bh, out);
}

// round 15
// speedup vs baseline: 5.7217x; 1.0022x over previous
#include <cuda_runtime.h>
#include <cuda_fp16.h>
#include <cstdint>

#define NN 100000
#define DD 128
#define EE 1600000
#define SPH 136    // smem row stride in halves for fp16 mma staging (128+8)
#define SP 132     // padded smem row stride (floats) for head tf32 staging
#define SP2 68     // padded stride for head weight rows (64 cols)

// ---------------- scratch (device globals; no allocations allowed) ----------
__device__ __align__(16) __half g_agg [(size_t)NN * DD]; // fp16 aggregation
__device__ __align__(16) float  g_hpre[(size_t)NN * DD]; // pre-BN activations
__device__ __align__(16) __half g_f16 [(size_t)NN * DD]; // fp16 feature buffer
__device__ int   g_deg   [NN];
__device__ int   g_cursor[NN];
__device__ int   g_rowptr[NN + 1];
__device__ int   g_col   [2 * EE];
__device__ float g_colsum[DD];
__device__ float g_colsq [DD];
__device__ __align__(16) float g_scale[DD];
__device__ __align__(16) float g_shift[DD];

// ---------------- CSR build --------------------------------------------------
__global__ void zero_kernel() {
    int i = blockIdx.x * blockDim.x + threadIdx.x;
    if (i < NN) { g_deg[i] = 0; g_cursor[i] = 0; }
    if (i < DD) { g_colsum[i] = 0.f; g_colsq[i] = 0.f; }
}

__global__ void count_kernel(const int* __restrict__ ei) {
    int e = blockIdx.x * blockDim.x + threadIdx.x;
    if (e >= EE) return;
    int a = ei[e], b = ei[EE + e];
    atomicAdd(&g_deg[a], 1);
    atomicAdd(&g_deg[b], 1);
}

// single-block scan over g_deg -> g_rowptr
__global__ void scan_kernel() {
    __shared__ int warp_sums[32];
    int tid = threadIdx.x;            // 1024 threads
    int lane = tid & 31, wid = tid >> 5;
    int running = 0;
    for (int base = 0; base < NN; base += 1024) {
        int i = base + tid;
        int v = (i < NN) ? g_deg[i] : 0;
        int x = v;
        #pragma unroll
        for (int o = 1; o < 32; o <<= 1) {
            int y = __shfl_up_sync(0xffffffffu, x, o);
            if (lane >= o) x += y;
        }
        if (lane == 31) warp_sums[wid] = x;
        __syncthreads();
        if (wid == 0) {
            int s = warp_sums[lane];
            #pragma unroll
            for (int o = 1; o < 32; o <<= 1) {
                int y = __shfl_up_sync(0xffffffffu, s, o);
                if (lane >= o) s += y;
            }
            warp_sums[lane] = s;
        }
        __syncthreads();
        int incl = running + (wid > 0 ? warp_sums[wid - 1] : 0) + x;
        if (i < NN) g_rowptr[i + 1] = incl;
        running += warp_sums[31];
        __syncthreads();
    }
    if (tid == 0) g_rowptr[0] = 0;
}

__global__ void scatter_kernel(const int* __restrict__ ei) {
    int e = blockIdx.x * blockDim.x + threadIdx.x;
    if (e >= EE) return;
    int a = ei[e], b = ei[EE + e];
    int pb = g_rowptr[b] + atomicAdd(&g_cursor[b], 1);
    g_col[pb] = a;
    int pa = g_rowptr[a] + atomicAdd(&g_cursor[a], 1);
    g_col[pa] = b;
}

// ---------------- fp16 conversion passes -------------------------------------
// MODE 0: g_f16 = fp16(x).  MODE 1: g_f16 = fp16(relu(bn(g_hpre))).
template<int MODE>
__global__ void tohalf_kernel(const float* __restrict__ xin) {
    int idx = blockIdx.x * blockDim.x + threadIdx.x;
    if (idx >= NN * 32) return;
    float4 v;
    if (MODE == 0) {
        v = ((const float4*)xin)[idx];
    } else {
        v = ((const float4*)g_hpre)[idx];
        int q = idx & 31;
        float4 sc = *(const float4*)(g_scale + q * 4);
        float4 sh = *(const float4*)(g_shift + q * 4);
        v.x = fmaxf(v.x * sc.x + sh.x, 0.f);
        v.y = fmaxf(v.y * sc.y + sh.y, 0.f);
        v.z = fmaxf(v.z * sc.z + sh.z, 0.f);
        v.w = fmaxf(v.w * sc.w + sh.w, 0.f);
    }
    __half2 h0 = __float22half2_rn(make_float2(v.x, v.y));
    __half2 h1 = __float22half2_rn(make_float2(v.z, v.w));
    uint2 o;
    o.x = *(uint32_t*)&h0;
    o.y = *(uint32_t*)&h1;
    ((uint2*)g_f16)[idx] = o;
}

// ---------------- aggregation: warp/node, 2 neighbors per LDG.128 ------------
// half 0 (lanes 0-15) fetches neighbor j, half 1 fetches j+1; lane covers 8
// consecutive cols (uint4 = 8 halves); shfl_xor(16) combines at the end.
__device__ __forceinline__ void acc8(float* acc, uint4 r) {
    __half2* h = (__half2*)&r;
    #pragma unroll
    for (int p = 0; p < 4; p++) {
        float2 f = __half22float2(h[p]);
        acc[p * 2 + 0] += f.x;
        acc[p * 2 + 1] += f.y;
    }
}

__global__ void __launch_bounds__(256) aggregate_kernel() {
    int node = (int)((blockIdx.x * blockDim.x + threadIdx.x) >> 5);
    if (node >= NN) return;
    int lane = threadIdx.x & 31;
    int half = lane >> 4, sub = lane & 15;
    const __half* base = g_f16 + (size_t)0;
    int coff = sub * 8;                       // column offset in halves

    float acc[8];
    #pragma unroll
    for (int r = 0; r < 8; r++) acc[r] = 0.f;

    if (half == 0)                            // self loop (half 0 only)
        acc8(acc, *(const uint4*)(base + (size_t)node * DD + coff));

    int s = g_rowptr[node];
    int e = g_rowptr[node + 1];
    int j = s;
    for (; j + 8 <= e; j += 8) {              // 4 pair-fetches in flight
        int n0 = g_col[j + 0 + half];
        int n1 = g_col[j + 2 + half];
        int n2 = g_col[j + 4 + half];
        int n3 = g_col[j + 6 + half];
        uint4 r0 = *(const uint4*)(base + (size_t)n0 * DD + coff);
        uint4 r1 = *(const uint4*)(base + (size_t)n1 * DD + coff);
        uint4 r2 = *(const uint4*)(base + (size_t)n2 * DD + coff);
        uint4 r3 = *(const uint4*)(base + (size_t)n3 * DD + coff);
        acc8(acc, r0); acc8(acc, r1); acc8(acc, r2); acc8(acc, r3);
    }
    for (; j + 2 <= e; j += 2) {
        int nb = g_col[j + half];
        acc8(acc, *(const uint4*)(base + (size_t)nb * DD + coff));
    }
    if (j < e && half == 0) {                 // odd remainder
        int nb = g_col[j];
        acc8(acc, *(const uint4*)(base + (size_t)nb * DD + coff));
    }

    #pragma unroll
    for (int r = 0; r < 8; r++)
        acc[r] += __shfl_xor_sync(0xffffffffu, acc[r], 16);

    if (half == 0) {
        float inv = 1.0f / (float)(e - s + 1);
        uint4 o;
        __half2* oh = (__half2*)&o;
        #pragma unroll
        for (int p = 0; p < 4; p++)
            oh[p] = __float22half2_rn(
                make_float2(acc[p * 2] * inv, acc[p * 2 + 1] * inv));
        *(uint4*)(g_agg + (size_t)node * DD + coff) = o;
    }
}

// ---------------- TF32 helpers (head only) -----------------------------------
__device__ __forceinline__ uint32_t f2tf32(float x) {
    uint32_t r;
    asm("cvt.rna.tf32.f32 %0, %1;" : "=r"(r) : "f"(x));
    return r;
}

__device__ __forceinline__ void mma_tf32(float* c, const uint32_t* a,
                                         const uint32_t* b) {
    asm volatile(
        "mma.sync.aligned.m16n8k8.row.col.f32.tf32.tf32.f32 "
        "{%0,%1,%2,%3}, {%4,%5,%6,%7}, {%8,%9}, {%0,%1,%2,%3};\n"
        : "+f"(c[0]), "+f"(c[1]), "+f"(c[2]), "+f"(c[3])
        : "r"(a[0]), "r"(a[1]), "r"(a[2]), "r"(a[3]), "r"(b[0]), "r"(b[1]));
}

// ---------------- fp16 mma helper --------------------------------------------
__device__ __forceinline__ void mma_f16(float* c, const uint32_t* a,
                                        const uint32_t* b) {
    asm volatile(
        "mma.sync.aligned.m16n8k16.row.col.f32.f16.f16.f32 "
        "{%0,%1,%2,%3}, {%4,%5,%6,%7}, {%8,%9}, {%0,%1,%2,%3};\n"
        : "+f"(c[0]), "+f"(c[1]), "+f"(c[2]), "+f"(c[3])
        : "r"(a[0]), "r"(a[1]), "r"(a[2]), "r"(a[3]), "r"(b[0]), "r"(b[1]));
}

// ---------------- fused dual GEMM via fp16 mma.sync --------------------------
// hpre = f16A@Wa^T + agg@Wb^T + bias.  A = g_f16 (fp16), B = g_agg (fp16).
// Weights stored [f][k] (no transpose), stride SPH halves (conflict-free).
__global__ void __launch_bounds__(512, 1) gemm_dual_kernel(
    const float* __restrict__ Wa, const float* __restrict__ Wb,
    const float* __restrict__ ba, const float* __restrict__ bb) {
    extern __shared__ __half smh[];
    __half* sWa  = smh;                  // 128 x SPH
    __half* sWb  = smh + 128 * SPH;      // 128 x SPH
    __half* sInA = smh + 256 * SPH;      // 128 x SPH
    __half* sInB = smh + 384 * SPH;      // 128 x SPH
    float*  sBias = (float*)(smh + 512 * SPH);   // 128 floats
    int tid = threadIdx.x;

    // stage weights as fp16, [f][k] layout (rows copied directly)
    for (int i = tid; i < 128 * 16; i += 512) {  // 8 floats per item
        int f = i >> 4, q = i & 15;
        const float4* wa = (const float4*)(Wa + f * DD + q * 8);
        const float4* wb = (const float4*)(Wb + f * DD + q * 8);
        float4 a0 = wa[0], a1 = wa[1];
        float4 b0 = wb[0], b1 = wb[1];
        uint4 oa, ob;
        __half2* ha = (__half2*)&oa;
        __half2* hb = (__half2*)&ob;
        ha[0] = __float22half2_rn(make_float2(a0.x, a0.y));
        ha[1] = __float22half2_rn(make_float2(a0.z, a0.w));
        ha[2] = __float22half2_rn(make_float2(a1.x, a1.y));
        ha[3] = __float22half2_rn(make_float2(a1.z, a1.w));
        hb[0] = __float22half2_rn(make_float2(b0.x, b0.y));
        hb[1] = __float22half2_rn(make_float2(b0.z, b0.w));
        hb[2] = __float22half2_rn(make_float2(b1.x, b1.y));
        hb[3] = __float22half2_rn(make_float2(b1.z, b1.w));
        *(uint4*)(sWa + f * SPH + q * 8) = oa;
        *(uint4*)(sWb + f * SPH + q * 8) = ob;
    }
    if (tid < DD) sBias[tid] = ba[tid] + bb[tid];

    int warp = tid >> 5, lane = tid & 31;
    int warpM = warp & 3, warpN = warp >> 2;      // 4x4 warp grid
    int g = lane >> 2, t = lane & 3;
    int cb = warpN * 32;                          // warp's col base

    float csum[4][2], csq[4][2];                  // BN partials (persist)
    #pragma unroll
    for (int n = 0; n < 4; n++) {
        csum[n][0] = csum[n][1] = 0.f;
        csq[n][0]  = csq[n][1]  = 0.f;
    }

    const int NT = (NN + 127) / 128;
    for (int tile = blockIdx.x; tile < NT; tile += gridDim.x) {
        int base = tile * 128;
        __syncthreads();   // prev tile consumed (covers weight/bias 1st use)

        // stage A (g_f16) and B (g_agg) rows: straight uint4 copies
        for (int i = tid; i < 128 * 16; i += 512) {
            int n = i >> 4, q = i & 15;
            int node = base + n;
            uint4 va = make_uint4(0, 0, 0, 0), vb = make_uint4(0, 0, 0, 0);
            if (node < NN) {
                va = *(const uint4*)(g_f16 + (size_t)node * DD + q * 8);
                vb = *(const uint4*)(g_agg + (size_t)node * DD + q * 8);
            }
            *(uint4*)(sInA + n * SPH + q * 8) = va;
            *(uint4*)(sInB + n * SPH + q * 8) = vb;
        }
        __syncthreads();

        float C[2][4][4];
        #pragma unroll
        for (int m = 0; m < 2; m++)
            #pragma unroll
            for (int n = 0; n < 4; n++)
                #pragma unroll
                for (int r = 0; r < 4; r++) C[m][n][r] = 0.f;

        #pragma unroll
        for (int ks = 0; ks < 16; ks++) {
            const __half* in = (ks < 8) ? sInA : sInB;
            const __half* ws = (ks < 8) ? sWa : sWb;
            int k = (ks & 7) * 16;
            uint32_t a[2][4];
            #pragma unroll
            for (int m = 0; m < 2; m++) {
                const __half* ap = in + (warpM * 32 + m * 16 + g) * SPH + k + 2 * t;
                a[m][0] = *(const uint32_t*)(ap);
                a[m][1] = *(const uint32_t*)(ap + 8 * SPH);
                a[m][2] = *(const uint32_t*)(ap + 8);
                a[m][3] = *(const uint32_t*)(ap + 8 * SPH + 8);
            }
            uint32_t b[4][2];
            #pragma unroll
            for (int n = 0; n < 4; n++) {
                const __half* bp = ws + (cb + n * 8 + g) * SPH + k + 2 * t;
                b[n][0] = *(const uint32_t*)(bp);
                b[n][1] = *(const uint32_t*)(bp + 8);
            }
            #pragma unroll
            for (int m = 0; m < 2; m++)
                #pragma unroll
                for (int n = 0; n < 4; n++)
                    mma_f16(C[m][n], a[m], b[n]);
        }

        // epilogue: bias add, store fp32 hpre, BN partials (only valid rows)
        #pragma unroll
        for (int m = 0; m < 2; m++) {
            int r0 = base + warpM * 32 + m * 16 + g;
            int r1 = r0 + 8;
            #pragma unroll
            for (int n = 0; n < 4; n++) {
                int col = cb + n * 8 + 2 * t;
                float b0v = sBias[col], b1v = sBias[col + 1];
                float v0 = C[m][n][0] + b0v, v1 = C[m][n][1] + b1v;
                float v2 = C[m][n][2] + b0v, v3 = C[m][n][3] + b1v;
                if (r0 < NN) {
                    *(float2*)(g_hpre + (size_t)r0 * DD + col) =
                        make_float2(v0, v1);
                    csum[n][0] += v0; csq[n][0] += v0 * v0;
                    csum[n][1] += v1; csq[n][1] += v1 * v1;
                }
                if (r1 < NN) {
                    *(float2*)(g_hpre + (size_t)r1 * DD + col) =
                        make_float2(v2, v3);
                    csum[n][0] += v2; csq[n][0] += v2 * v2;
                    csum[n][1] += v3; csq[n][1] += v3 * v3;
                }
            }
        }
    }

    // shfl-reduce BN partials over g (lanes sharing a column), then atomics
    #pragma unroll
    for (int n = 0; n < 4; n++)
        #pragma unroll
        for (int c = 0; c < 2; c++) {
            float s = csum[n][c], q = csq[n][c];
            #pragma unroll
            for (int o = 4; o < 32; o <<= 1) {
                s += __shfl_xor_sync(0xffffffffu, s, o);
                q += __shfl_xor_sync(0xffffffffu, q, o);
            }
            if (g == 0) {
                int col = cb + n * 8 + 2 * t + c;
                atomicAdd(&g_colsum[col], s);
                atomicAdd(&g_colsq[col], q);
            }
        }
}

// ---------------- BN finalize: stats -> scale/shift, reset stats ------------
__global__ void bn_finalize_kernel(const float* __restrict__ gamma,
                                   const float* __restrict__ beta) {
    int c = threadIdx.x;
    float mean = g_colsum[c] * (1.0f / NN);
    float var  = g_colsq[c]  * (1.0f / NN) - mean * mean;
    float sc   = gamma[c] * rsqrtf(var + 1e-5f);
    g_scale[c] = sc;
    g_shift[c] = beta[c] - mean * sc;
    g_colsum[c] = 0.f;
    g_colsq[c]  = 0.f;
}

// ---------------- head via TF32 mma: out = relu(bn(hpre)) @ Wh^T + bh -------
// 256 thr = 8 warps (4M x 2N); 128-node tile per block; K=128.
__global__ void __launch_bounds__(256) head_kernel(
    const float* __restrict__ Wh, const float* __restrict__ bh,
    float* __restrict__ outp) {
    extern __shared__ float sm[];
    float* sW  = sm;              // 128 x SP2 (tf32 bits, [k][f])
    float* sIn = sm + DD * SP2;   // 128 x SP  (tf32 bits, [node][k])
    int tid = threadIdx.x;

    for (int i = tid; i < 64 * DD; i += 256) {
        int f = i >> 7, k = i & 127;
        sW[k * SP2 + f] = __uint_as_float(f2tf32(Wh[i]));
    }

    int base = blockIdx.x * 128;
    for (int i = tid; i < 128 * 32; i += 256) {
        int n = i >> 5, q = i & 31;
        int node = base + n;
        float4 v = make_float4(0.f, 0.f, 0.f, 0.f);
        if (node < NN) {
            v = *(const float4*)(g_hpre + (size_t)node * DD + q * 4);
            float4 sc = *(const float4*)(g_scale + q * 4);
            float4 sh = *(const float4*)(g_shift + q * 4);
            v.x = fmaxf(v.x * sc.x + sh.x, 0.f);
            v.y = fmaxf(v.y * sc.y + sh.y, 0.f);
            v.z = fmaxf(v.z * sc.z + sh.z, 0.f);
            v.w = fmaxf(v.w * sc.w + sh.w, 0.f);
        }
        float4 o;
        o.x = __uint_as_float(f2tf32(v.x));
        o.y = __uint_as_float(f2tf32(v.y));
        o.z = __uint_as_float(f2tf32(v.z));
        o.w = __uint_as_float(f2tf32(v.w));
        *(float4*)(sIn + n * SP + q * 4) = o;
    }
    __syncthreads();

    int warp = tid >> 5, lane = tid & 31;
    int warpM = warp & 3, warpN = warp >> 2;   // 4 x 2
    int g = lane >> 2, t = lane & 3;
    int cb = warpN * 32;

    float C[2][4][4];
    #pragma unroll
    for (int m = 0; m < 2; m++)
        #pragma unroll
        for (int n = 0; n < 4; n++)
            #pragma unroll
            for (int r = 0; r < 4; r++) C[m][n][r] = 0.f;

    #pragma unroll
    for (int kk = 0; kk < 16; kk++) {
        int k = kk * 8;
        uint32_t a[2][4];
        #pragma unroll
        for (int m = 0; m < 2; m++) {
            const float* ap = sIn + (warpM * 32 + m * 16 + g) * SP + k + t;
            a[m][0] = __float_as_uint(ap[0]);
            a[m][1] = __float_as_uint(ap[8 * SP]);
            a[m][2] = __float_as_uint(ap[4]);
            a[m][3] = __float_as_uint(ap[8 * SP + 4]);
        }
        uint32_t b[4][2];
        #pragma unroll
        for (int n = 0; n < 4; n++) {
            const float* bp = sW + (k + t) * SP2 + cb + n * 8 + g;
            b[n][0] = __float_as_uint(bp[0]);
            b[n][1] = __float_as_uint(bp[4 * SP2]);
        }
        #pragma unroll
        for (int m = 0; m < 2; m++)
            #pragma unroll
            for (int n = 0; n < 4; n++)
                mma_tf32(C[m][n], a[m], b[n]);
    }

    #pragma unroll
    for (int m = 0; m < 2; m++) {
        int r0 = base + warpM * 32 + m * 16 + g;
        int r1 = r0 + 8;
        #pragma unroll
        for (int n = 0; n < 4; n++) {
            int col = cb + n * 8 + 2 * t;
            float b0v = bh[col], b1v = bh[col + 1];
            if (r0 < NN)
                *(float2*)(outp + (size_t)r0 * 64 + col) =
                    make_float2(C[m][n][0] + b0v, C[m][n][1] + b1v);
            if (r1 < NN)
                *(float2*)(outp + (size_t)r1 * 64 + col) =
                    make_float2(C[m][n][2] + b0v, C[m][n][3] + b1v);
        }
    }
}

// ---------------- launch ----------------------------------------------------
extern "C" void kernel_launch(void* const* d_in, const int* in_sizes, int n_in,
                              void* d_out, int out_size) {
    const float* x   = (const float*)d_in[0];
    const int*   ei  = (const int*)d_in[1];     // int32 (JAX default int)
    const float* Ws1 = (const float*)d_in[2];
    const float* bs1 = (const float*)d_in[3];
    const float* Wn1 = (const float*)d_in[4];
    const float* bn1 = (const float*)d_in[5];
    const float* g1  = (const float*)d_in[6];
    const float* be1 = (const float*)d_in[7];
    const float* Ws2 = (const float*)d_in[8];
    const float* bs2 = (const float*)d_in[9];
    const float* Wn2 = (const float*)d_in[10];
    const float* bn2 = (const float*)d_in[11];
    const float* g2  = (const float*)d_in[12];
    const float* be2 = (const float*)d_in[13];
    const float* Wh  = (const float*)d_in[14];
    const float* bh  = (const float*)d_in[15];
    float* out = (float*)d_out;

    const int GEMM_SMEM = 512 * SPH * 2 + 128 * 4;           // 139776+512 B
    const int HEAD_SMEM = (DD * SP2 + 128 * SP) * 4;         // 102400 B
    cudaFuncSetAttribute(gemm_dual_kernel,
                         cudaFuncAttributeMaxDynamicSharedMemorySize, GEMM_SMEM);
    cudaFuncSetAttribute(head_kernel,
                         cudaFuncAttributeMaxDynamicSharedMemorySize, HEAD_SMEM);

    const int NT32 = (NN * 32 + 255) / 256;

    // CSR build (once; reused by both layers)
    zero_kernel<<<(NN + 255) / 256, 256>>>();
    count_kernel<<<(EE + 255) / 256, 256>>>(ei);
    scan_kernel<<<1, 1024>>>();
    scatter_kernel<<<(EE + 255) / 256, 256>>>(ei);

    // layer 1: fp16(x) -> gather -> dual gemm -> bn stats
    tohalf_kernel<0><<<NT32, 256>>>(x);
    aggregate_kernel<<<NT32, 256>>>();
    gemm_dual_kernel<<<148, 512, GEMM_SMEM>>>(Ws1, Wn1, bs1, bn1);
    bn_finalize_kernel<<<1, 128>>>(g1, be1);

    // layer 2: fp16(relu(bn(hpre))) -> gather -> dual gemm -> bn stats
    tohalf_kernel<1><<<NT32, 256>>>(x);
    aggregate_kernel<<<NT32, 256>>>();
    gemm_dual_kernel<<<148, 512, GEMM_SMEM>>>(Ws2, Wn2, bs2, bn2);
    bn_finalize_kernel<<<1, 128>>>(g2, be2);

    // head (BN+ReLU of layer 2 applied on the fly)
    head_kernel<<<(NN + 127) / 128, 256, HEAD_SMEM>>>(Wh, bh, out);
}

// round 16
// speedup vs baseline: 5.7496x; 1.0049x over previous
#include <cuda_runtime.h>
#include <cuda_fp16.h>
#include <cstdint>

#define NN 100000
#define DD 128
#define EE 1600000
#define SPH 136    // smem row stride in halves for fp16 mma staging (128+8)
#define SP 132     // padded smem row stride (floats) for head tf32 staging
#define SP2 68     // padded stride for head weight rows (64 cols)

// ---------------- scratch (device globals; no allocations allowed) ----------
// g_f16 holds, in sequence: fp16(x) -> fp16(hpre1) -> fp16(hpre2) (in-place).
__device__ __align__(16) __half g_agg [(size_t)NN * DD]; // fp16 aggregation
__device__ __align__(16) __half g_f16 [(size_t)NN * DD]; // fp16 feature buffer
__device__ int   g_deg   [NN];
__device__ int   g_cursor[NN];
__device__ int   g_rowptr[NN + 1];
__device__ int   g_col   [2 * EE];
__device__ float g_colsum[DD];
__device__ float g_colsq [DD];
__device__ __align__(16) float g_scale[DD];
__device__ __align__(16) float g_shift[DD];

// ---------------- CSR build --------------------------------------------------
__global__ void zero_kernel() {
    int i = blockIdx.x * blockDim.x + threadIdx.x;
    if (i < NN) { g_deg[i] = 0; g_cursor[i] = 0; }
    if (i < DD) { g_colsum[i] = 0.f; g_colsq[i] = 0.f; }
}

__global__ void count_kernel(const int* __restrict__ ei) {
    int e = blockIdx.x * blockDim.x + threadIdx.x;
    if (e >= EE) return;
    int a = ei[e], b = ei[EE + e];
    atomicAdd(&g_deg[a], 1);
    atomicAdd(&g_deg[b], 1);
}

// block 0: single-block scan over g_deg -> g_rowptr.
// blocks 1..3125: g_f16 = fp16(x)  (3125*1024 = NN*32 exactly)
__global__ void __launch_bounds__(1024) scan_tohalf_kernel(
    const float* __restrict__ xin) {
    int tid = threadIdx.x;
    if (blockIdx.x != 0) {
        int idx = (blockIdx.x - 1) * 1024 + tid;
        if (idx < NN * 32) {
            float4 v = ((const float4*)xin)[idx];
            __half2 h0 = __float22half2_rn(make_float2(v.x, v.y));
            __half2 h1 = __float22half2_rn(make_float2(v.z, v.w));
            uint2 o;
            o.x = *(uint32_t*)&h0;
            o.y = *(uint32_t*)&h1;
            ((uint2*)g_f16)[idx] = o;
        }
        return;
    }
    __shared__ int warp_sums[32];
    int lane = tid & 31, wid = tid >> 5;
    int running = 0;
    for (int base = 0; base < NN; base += 1024) {
        int i = base + tid;
        int v = (i < NN) ? g_deg[i] : 0;
        int x = v;
        #pragma unroll
        for (int o = 1; o < 32; o <<= 1) {
            int y = __shfl_up_sync(0xffffffffu, x, o);
            if (lane >= o) x += y;
        }
        if (lane == 31) warp_sums[wid] = x;
        __syncthreads();
        if (wid == 0) {
            int s = warp_sums[lane];
            #pragma unroll
            for (int o = 1; o < 32; o <<= 1) {
                int y = __shfl_up_sync(0xffffffffu, s, o);
                if (lane >= o) s += y;
            }
            warp_sums[lane] = s;
        }
        __syncthreads();
        int incl = running + (wid > 0 ? warp_sums[wid - 1] : 0) + x;
        if (i < NN) g_rowptr[i + 1] = incl;
        running += warp_sums[31];
        __syncthreads();
    }
    if (tid == 0) g_rowptr[0] = 0;
}

__global__ void scatter_kernel(const int* __restrict__ ei) {
    int e = blockIdx.x * blockDim.x + threadIdx.x;
    if (e >= EE) return;
    int a = ei[e], b = ei[EE + e];
    int pb = g_rowptr[b] + atomicAdd(&g_cursor[b], 1);
    g_col[pb] = a;
    int pa = g_rowptr[a] + atomicAdd(&g_cursor[a], 1);
    g_col[pa] = b;
}

// ---------------- aggregation: warp/node, 2 neighbors per LDG.128 ------------
// BN=true applies relu(v*scale+shift) per gathered element (layer-2 path).
template<bool BN>
__device__ __forceinline__ void acc8(float* acc, uint4 r,
                                     const float* sc, const float* sh) {
    __half2* h = (__half2*)&r;
    #pragma unroll
    for (int p = 0; p < 4; p++) {
        float2 f = __half22float2(h[p]);
        if (BN) {
            f.x = fmaxf(f.x * sc[2 * p]     + sh[2 * p],     0.f);
            f.y = fmaxf(f.y * sc[2 * p + 1] + sh[2 * p + 1], 0.f);
        }
        acc[2 * p]     += f.x;
        acc[2 * p + 1] += f.y;
    }
}

template<bool BN>
__global__ void __launch_bounds__(256) aggregate_kernel() {
    int node = (int)((blockIdx.x * blockDim.x + threadIdx.x) >> 5);
    if (node >= NN) return;
    int lane = threadIdx.x & 31;
    int half = lane >> 4, sub = lane & 15;
    const __half* base = g_f16;
    int coff = sub * 8;                       // column offset in halves

    float sc[8], sh[8];
    if (BN) {
        *(float4*)(sc)     = *(const float4*)(g_scale + coff);
        *(float4*)(sc + 4) = *(const float4*)(g_scale + coff + 4);
        *(float4*)(sh)     = *(const float4*)(g_shift + coff);
        *(float4*)(sh + 4) = *(const float4*)(g_shift + coff + 4);
    }

    float acc[8];
    #pragma unroll
    for (int r = 0; r < 8; r++) acc[r] = 0.f;

    if (half == 0)                            // self loop (half 0 only)
        acc8<BN>(acc, *(const uint4*)(base + (size_t)node * DD + coff), sc, sh);

    int s = g_rowptr[node];
    int e = g_rowptr[node + 1];
    int j = s;
    for (; j + 8 <= e; j += 8) {              // 4 pair-fetches in flight
        int n0 = g_col[j + 0 + half];
        int n1 = g_col[j + 2 + half];
        int n2 = g_col[j + 4 + half];
        int n3 = g_col[j + 6 + half];
        uint4 r0 = *(const uint4*)(base + (size_t)n0 * DD + coff);
        uint4 r1 = *(const uint4*)(base + (size_t)n1 * DD + coff);
        uint4 r2 = *(const uint4*)(base + (size_t)n2 * DD + coff);
        uint4 r3 = *(const uint4*)(base + (size_t)n3 * DD + coff);
        acc8<BN>(acc, r0, sc, sh); acc8<BN>(acc, r1, sc, sh);
        acc8<BN>(acc, r2, sc, sh); acc8<BN>(acc, r3, sc, sh);
    }
    for (; j + 2 <= e; j += 2) {
        int nb = g_col[j + half];
        acc8<BN>(acc, *(const uint4*)(base + (size_t)nb * DD + coff), sc, sh);
    }
    if (j < e && half == 0) {                 // odd remainder
        int nb = g_col[j];
        acc8<BN>(acc, *(const uint4*)(base + (size_t)nb * DD + coff), sc, sh);
    }

    #pragma unroll
    for (int r = 0; r < 8; r++)
        acc[r] += __shfl_xor_sync(0xffffffffu, acc[r], 16);

    if (half == 0) {
        float inv = 1.0f / (float)(e - s + 1);
        uint4 o;
        __half2* oh = (__half2*)&o;
        #pragma unroll
        for (int p = 0; p < 4; p++)
            oh[p] = __float22half2_rn(
                make_float2(acc[p * 2] * inv, acc[p * 2 + 1] * inv));
        *(uint4*)(g_agg + (size_t)node * DD + coff) = o;
    }
}

// ---------------- TF32 helpers (head only) -----------------------------------
__device__ __forceinline__ uint32_t f2tf32(float x) {
    uint32_t r;
    asm("cvt.rna.tf32.f32 %0, %1;" : "=r"(r) : "f"(x));
    return r;
}

__device__ __forceinline__ void mma_tf32(float* c, const uint32_t* a,
                                         const uint32_t* b) {
    asm volatile(
        "mma.sync.aligned.m16n8k8.row.col.f32.tf32.tf32.f32 "
        "{%0,%1,%2,%3}, {%4,%5,%6,%7}, {%8,%9}, {%0,%1,%2,%3};\n"
        : "+f"(c[0]), "+f"(c[1]), "+f"(c[2]), "+f"(c[3])
        : "r"(a[0]), "r"(a[1]), "r"(a[2]), "r"(a[3]), "r"(b[0]), "r"(b[1]));
}

// ---------------- fp16 mma helper --------------------------------------------
__device__ __forceinline__ void mma_f16(float* c, const uint32_t* a,
                                        const uint32_t* b) {
    asm volatile(
        "mma.sync.aligned.m16n8k16.row.col.f32.f16.f16.f32 "
        "{%0,%1,%2,%3}, {%4,%5,%6,%7}, {%8,%9}, {%0,%1,%2,%3};\n"
        : "+f"(c[0]), "+f"(c[1]), "+f"(c[2]), "+f"(c[3])
        : "r"(a[0]), "r"(a[1]), "r"(a[2]), "r"(a[3]), "r"(b[0]), "r"(b[1]));
}

// ---------------- fused dual GEMM via fp16 mma.sync --------------------------
// hpre = A@Wa^T + agg@Wb^T + bias.  A = g_f16; LAYER 1 applies BN+ReLU to A at
// staging. Epilogue writes fp16(hpre) IN-PLACE into g_f16 (same-block rows).
template<int LAYER>
__global__ void __launch_bounds__(512, 1) gemm_dual_kernel(
    const float* __restrict__ Wa, const float* __restrict__ Wb,
    const float* __restrict__ ba, const float* __restrict__ bb) {
    extern __shared__ __half smh[];
    __half* sWa  = smh;                  // 128 x SPH
    __half* sWb  = smh + 128 * SPH;      // 128 x SPH
    __half* sInA = smh + 256 * SPH;      // 128 x SPH
    __half* sInB = smh + 384 * SPH;      // 128 x SPH
    float*  sBias = (float*)(smh + 512 * SPH);   // 128 floats
    int tid = threadIdx.x;

    // stage weights as fp16, [f][k] layout (rows copied directly)
    for (int i = tid; i < 128 * 16; i += 512) {  // 8 floats per item
        int f = i >> 4, q = i & 15;
        const float4* wa = (const float4*)(Wa + f * DD + q * 8);
        const float4* wb = (const float4*)(Wb + f * DD + q * 8);
        float4 a0 = wa[0], a1 = wa[1];
        float4 b0 = wb[0], b1 = wb[1];
        uint4 oa, ob;
        __half2* ha = (__half2*)&oa;
        __half2* hb = (__half2*)&ob;
        ha[0] = __float22half2_rn(make_float2(a0.x, a0.y));
        ha[1] = __float22half2_rn(make_float2(a0.z, a0.w));
        ha[2] = __float22half2_rn(make_float2(a1.x, a1.y));
        ha[3] = __float22half2_rn(make_float2(a1.z, a1.w));
        hb[0] = __float22half2_rn(make_float2(b0.x, b0.y));
        hb[1] = __float22half2_rn(make_float2(b0.z, b0.w));
        hb[2] = __float22half2_rn(make_float2(b1.x, b1.y));
        hb[3] = __float22half2_rn(make_float2(b1.z, b1.w));
        *(uint4*)(sWa + f * SPH + q * 8) = oa;
        *(uint4*)(sWb + f * SPH + q * 8) = ob;
    }
    if (tid < DD) sBias[tid] = ba[tid] + bb[tid];

    int warp = tid >> 5, lane = tid & 31;
    int warpM = warp & 3, warpN = warp >> 2;      // 4x4 warp grid
    int g = lane >> 2, t = lane & 3;
    int cb = warpN * 32;                          // warp's col base

    float csum[4][2], csq[4][2];                  // BN partials (persist)
    #pragma unroll
    for (int n = 0; n < 4; n++) {
        csum[n][0] = csum[n][1] = 0.f;
        csq[n][0]  = csq[n][1]  = 0.f;
    }

    const int NT = (NN + 127) / 128;
    for (int tile = blockIdx.x; tile < NT; tile += gridDim.x) {
        int base = tile * 128;
        __syncthreads();   // prev tile consumed (covers weight/bias 1st use)

        // stage A (g_f16, BN for LAYER 1) and B (g_agg) rows
        for (int i = tid; i < 128 * 16; i += 512) {
            int n = i >> 4, q = i & 15;
            int node = base + n;
            uint4 va = make_uint4(0, 0, 0, 0), vb = make_uint4(0, 0, 0, 0);
            if (node < NN) {
                va = *(const uint4*)(g_f16 + (size_t)node * DD + q * 8);
                vb = *(const uint4*)(g_agg + (size_t)node * DD + q * 8);
            }
            if (LAYER == 1) {   // A = fp16(relu(bn(hpre1)))
                float4 sc0 = *(const float4*)(g_scale + q * 8);
                float4 sc1 = *(const float4*)(g_scale + q * 8 + 4);
                float4 sh0 = *(const float4*)(g_shift + q * 8);
                float4 sh1 = *(const float4*)(g_shift + q * 8 + 4);
                __half2* hv = (__half2*)&va;
                float2 f0 = __half22float2(hv[0]);
                float2 f1 = __half22float2(hv[1]);
                float2 f2 = __half22float2(hv[2]);
                float2 f3 = __half22float2(hv[3]);
                f0.x = fmaxf(f0.x * sc0.x + sh0.x, 0.f);
                f0.y = fmaxf(f0.y * sc0.y + sh0.y, 0.f);
                f1.x = fmaxf(f1.x * sc0.z + sh0.z, 0.f);
                f1.y = fmaxf(f1.y * sc0.w + sh0.w, 0.f);
                f2.x = fmaxf(f2.x * sc1.x + sh1.x, 0.f);
                f2.y = fmaxf(f2.y * sc1.y + sh1.y, 0.f);
                f3.x = fmaxf(f3.x * sc1.z + sh1.z, 0.f);
                f3.y = fmaxf(f3.y * sc1.w + sh1.w, 0.f);
                hv[0] = __float22half2_rn(f0);
                hv[1] = __float22half2_rn(f1);
                hv[2] = __float22half2_rn(f2);
                hv[3] = __float22half2_rn(f3);
            }
            *(uint4*)(sInA + n * SPH + q * 8) = va;
            *(uint4*)(sInB + n * SPH + q * 8) = vb;
        }
        __syncthreads();

        float C[2][4][4];
        #pragma unroll
        for (int m = 0; m < 2; m++)
            #pragma unroll
            for (int n = 0; n < 4; n++)
                #pragma unroll
                for (int r = 0; r < 4; r++) C[m][n][r] = 0.f;

        #pragma unroll
        for (int ks = 0; ks < 16; ks++) {
            const __half* in = (ks < 8) ? sInA : sInB;
            const __half* ws = (ks < 8) ? sWa : sWb;
            int k = (ks & 7) * 16;
            uint32_t a[2][4];
            #pragma unroll
            for (int m = 0; m < 2; m++) {
                const __half* ap = in + (warpM * 32 + m * 16 + g) * SPH + k + 2 * t;
                a[m][0] = *(const uint32_t*)(ap);
                a[m][1] = *(const uint32_t*)(ap + 8 * SPH);
                a[m][2] = *(const uint32_t*)(ap + 8);
                a[m][3] = *(const uint32_t*)(ap + 8 * SPH + 8);
            }
            uint32_t b[4][2];
            #pragma unroll
            for (int n = 0; n < 4; n++) {
                const __half* bp = ws + (cb + n * 8 + g) * SPH + k + 2 * t;
                b[n][0] = *(const uint32_t*)(bp);
                b[n][1] = *(const uint32_t*)(bp + 8);
            }
            #pragma unroll
            for (int m = 0; m < 2; m++)
                #pragma unroll
                for (int n = 0; n < 4; n++)
                    mma_f16(C[m][n], a[m], b[n]);
        }

        // epilogue: bias add, write fp16(hpre) in-place, BN partials (fp32)
        #pragma unroll
        for (int m = 0; m < 2; m++) {
            int r0 = base + warpM * 32 + m * 16 + g;
            int r1 = r0 + 8;
            #pragma unroll
            for (int n = 0; n < 4; n++) {
                int col = cb + n * 8 + 2 * t;
                float b0v = sBias[col], b1v = sBias[col + 1];
                float v0 = C[m][n][0] + b0v, v1 = C[m][n][1] + b1v;
                float v2 = C[m][n][2] + b0v, v3 = C[m][n][3] + b1v;
                if (r0 < NN) {
                    *(__half2*)(g_f16 + (size_t)r0 * DD + col) =
                        __float22half2_rn(make_float2(v0, v1));
                    csum[n][0] += v0; csq[n][0] += v0 * v0;
                    csum[n][1] += v1; csq[n][1] += v1 * v1;
                }
                if (r1 < NN) {
                    *(__half2*)(g_f16 + (size_t)r1 * DD + col) =
                        __float22half2_rn(make_float2(v2, v3));
                    csum[n][0] += v2; csq[n][0] += v2 * v2;
                    csum[n][1] += v3; csq[n][1] += v3 * v3;
                }
            }
        }
    }

    // shfl-reduce BN partials over g (lanes sharing a column), then atomics
    #pragma unroll
    for (int n = 0; n < 4; n++)
        #pragma unroll
        for (int c = 0; c < 2; c++) {
            float s = csum[n][c], q = csq[n][c];
            #pragma unroll
            for (int o = 4; o < 32; o <<= 1) {
                s += __shfl_xor_sync(0xffffffffu, s, o);
                q += __shfl_xor_sync(0xffffffffu, q, o);
            }
            if (g == 0) {
                int col = cb + n * 8 + 2 * t + c;
                atomicAdd(&g_colsum[col], s);
                atomicAdd(&g_colsq[col], q);
            }
        }
}

// ---------------- BN finalize: stats -> scale/shift, reset stats ------------
__global__ void bn_finalize_kernel(const float* __restrict__ gamma,
                                   const float* __restrict__ beta) {
    int c = threadIdx.x;
    float mean = g_colsum[c] * (1.0f / NN);
    float var  = g_colsq[c]  * (1.0f / NN) - mean * mean;
    float sc   = gamma[c] * rsqrtf(var + 1e-5f);
    g_scale[c] = sc;
    g_shift[c] = beta[c] - mean * sc;
    g_colsum[c] = 0.f;
    g_colsq[c]  = 0.f;
}

// ---------------- head via TF32 mma: out = relu(bn2(hpre2)) @ Wh^T + bh ------
// reads fp16 hpre2 from g_f16, BN applied at staging. 256 thr, 128-node tile.
__global__ void __launch_bounds__(256) head_kernel(
    const float* __restrict__ Wh, const float* __restrict__ bh,
    float* __restrict__ outp) {
    extern __shared__ float sm[];
    float* sW  = sm;              // 128 x SP2 (tf32 bits, [k][f])
    float* sIn = sm + DD * SP2;   // 128 x SP  (tf32 bits, [node][k])
    int tid = threadIdx.x;

    for (int i = tid; i < 64 * DD; i += 256) {
        int f = i >> 7, k = i & 127;
        sW[k * SP2 + f] = __uint_as_float(f2tf32(Wh[i]));
    }

    int base = blockIdx.x * 128;
    for (int i = tid; i < 128 * 16; i += 256) {
        int n = i >> 4, q = i & 15;
        int node = base + n;
        float vals[8];
        #pragma unroll
        for (int p = 0; p < 8; p++) vals[p] = 0.f;
        if (node < NN) {
            uint4 r = *(const uint4*)(g_f16 + (size_t)node * DD + q * 8);
            float4 sc0 = *(const float4*)(g_scale + q * 8);
            float4 sc1 = *(const float4*)(g_scale + q * 8 + 4);
            float4 sh0 = *(const float4*)(g_shift + q * 8);
            float4 sh1 = *(const float4*)(g_shift + q * 8 + 4);
            __half2* hv = (__half2*)&r;
            float2 f0 = __half22float2(hv[0]);
            float2 f1 = __half22float2(hv[1]);
            float2 f2 = __half22float2(hv[2]);
            float2 f3 = __half22float2(hv[3]);
            vals[0] = fmaxf(f0.x * sc0.x + sh0.x, 0.f);
            vals[1] = fmaxf(f0.y * sc0.y + sh0.y, 0.f);
            vals[2] = fmaxf(f1.x * sc0.z + sh0.z, 0.f);
            vals[3] = fmaxf(f1.y * sc0.w + sh0.w, 0.f);
            vals[4] = fmaxf(f2.x * sc1.x + sh1.x, 0.f);
            vals[5] = fmaxf(f2.y * sc1.y + sh1.y, 0.f);
            vals[6] = fmaxf(f3.x * sc1.z + sh1.z, 0.f);
            vals[7] = fmaxf(f3.y * sc1.w + sh1.w, 0.f);
        }
        float4 o0, o1;
        o0.x = __uint_as_float(f2tf32(vals[0]));
        o0.y = __uint_as_float(f2tf32(vals[1]));
        o0.z = __uint_as_float(f2tf32(vals[2]));
        o0.w = __uint_as_float(f2tf32(vals[3]));
        o1.x = __uint_as_float(f2tf32(vals[4]));
        o1.y = __uint_as_float(f2tf32(vals[5]));
        o1.z = __uint_as_float(f2tf32(vals[6]));
        o1.w = __uint_as_float(f2tf32(vals[7]));
        *(float4*)(sIn + n * SP + q * 8)     = o0;
        *(float4*)(sIn + n * SP + q * 8 + 4) = o1;
    }
    __syncthreads();

    int warp = tid >> 5, lane = tid & 31;
    int warpM = warp & 3, warpN = warp >> 2;   // 4 x 2
    int g = lane >> 2, t = lane & 3;
    int cb = warpN * 32;

    float C[2][4][4];
    #pragma unroll
    for (int m = 0; m < 2; m++)
        #pragma unroll
        for (int n = 0; n < 4; n++)
            #pragma unroll
            for (int r = 0; r < 4; r++) C[m][n][r] = 0.f;

    #pragma unroll
    for (int kk = 0; kk < 16; kk++) {
        int k = kk * 8;
        uint32_t a[2][4];
        #pragma unroll
        for (int m = 0; m < 2; m++) {
            const float* ap = sIn + (warpM * 32 + m * 16 + g) * SP + k + t;
            a[m][0] = __float_as_uint(ap[0]);
            a[m][1] = __float_as_uint(ap[8 * SP]);
            a[m][2] = __float_as_uint(ap[4]);
            a[m][3] = __float_as_uint(ap[8 * SP + 4]);
        }
        uint32_t b[4][2];
        #pragma unroll
        for (int n = 0; n < 4; n++) {
            const float* bp = sW + (k + t) * SP2 + cb + n * 8 + g;
            b[n][0] = __float_as_uint(bp[0]);
            b[n][1] = __float_as_uint(bp[4 * SP2]);
        }
        #pragma unroll
        for (int m = 0; m < 2; m++)
            #pragma unroll
            for (int n = 0; n < 4; n++)
                mma_tf32(C[m][n], a[m], b[n]);
    }

    #pragma unroll
    for (int m = 0; m < 2; m++) {
        int r0 = base + warpM * 32 + m * 16 + g;
        int r1 = r0 + 8;
        #pragma unroll
        for (int n = 0; n < 4; n++) {
            int col = cb + n * 8 + 2 * t;
            float b0v = bh[col], b1v = bh[col + 1];
            if (r0 < NN)
                *(float2*)(outp + (size_t)r0 * 64 + col) =
                    make_float2(C[m][n][0] + b0v, C[m][n][1] + b1v);
            if (r1 < NN)
                *(float2*)(outp + (size_t)r1 * 64 + col) =
                    make_float2(C[m][n][2] + b0v, C[m][n][3] + b1v);
        }
    }
}

// ---------------- launch ----------------------------------------------------
extern "C" void kernel_launch(void* const* d_in, const int* in_sizes, int n_in,
                              void* d_out, int out_size) {
    const float* x   = (const float*)d_in[0];
    const int*   ei  = (const int*)d_in[1];     // int32 (JAX default int)
    const float* Ws1 = (const float*)d_in[2];
    const float* bs1 = (const float*)d_in[3];
    const float* Wn1 = (const float*)d_in[4];
    const float* bn1 = (const float*)d_in[5];
    const float* g1  = (const float*)d_in[6];
    const float* be1 = (const float*)d_in[7];
    const float* Ws2 = (const float*)d_in[8];
    const float* bs2 = (const float*)d_in[9];
    const float* Wn2 = (const float*)d_in[10];
    const float* bn2 = (const float*)d_in[11];
    const float* g2  = (const float*)d_in[12];
    const float* be2 = (const float*)d_in[13];
    const float* Wh  = (const float*)d_in[14];
    const float* bh  = (const float*)d_in[15];
    float* out = (float*)d_out;

    const int GEMM_SMEM = 512 * SPH * 2 + 128 * 4;           // 139776+512 B
    const int HEAD_SMEM = (DD * SP2 + 128 * SP) * 4;         // 102400 B
    cudaFuncSetAttribute(gemm_dual_kernel<0>,
                         cudaFuncAttributeMaxDynamicSharedMemorySize, GEMM_SMEM);
    cudaFuncSetAttribute(gemm_dual_kernel<1>,
                         cudaFuncAttributeMaxDynamicSharedMemorySize, GEMM_SMEM);
    cudaFuncSetAttribute(head_kernel,
                         cudaFuncAttributeMaxDynamicSharedMemorySize, HEAD_SMEM);

    const int NT32 = (NN * 32 + 255) / 256;

    // CSR build + fp16(x) conversion (scan block 0, tohalf blocks 1..3125)
    zero_kernel<<<(NN + 255) / 256, 256>>>();
    count_kernel<<<(EE + 255) / 256, 256>>>(ei);
    scan_tohalf_kernel<<<1 + (NN * 32 + 1023) / 1024, 1024>>>(x);
    scatter_kernel<<<(EE + 255) / 256, 256>>>(ei);

    // layer 1: gather raw fp16(x) -> dual gemm (writes fp16 hpre1 in-place)
    aggregate_kernel<false><<<NT32, 256>>>();
    gemm_dual_kernel<0><<<148, 512, GEMM_SMEM>>>(Ws1, Wn1, bs1, bn1);
    bn_finalize_kernel<<<1, 128>>>(g1, be1);

    // layer 2: gather with BN1+ReLU -> dual gemm (BN1 on A, writes hpre2)
    aggregate_kernel<true><<<NT32, 256>>>();
    gemm_dual_kernel<1><<<148, 512, GEMM_SMEM>>>(Ws2, Wn2, bs2, bn2);
    bn_finalize_kernel<<<1, 128>>>(g2, be2);

    // head (BN2+ReLU applied at staging)
    head_kernel<<<(NN + 127) / 128, 256, HEAD_SMEM>>>(Wh, bh, out);
}